// round 3
// baseline (speedup 1.0000x reference)
#include <cuda_runtime.h>
#include <cuda_fp16.h>
#include <cstdint>

#define N_TOKENS 4096
#define TOP_K    2
#define N_EXPERTS 8
#define HIDDEN   1024
#define INTER    2048
#define NSLOT    (N_TOKENS*TOP_K)            /* 8192 */
#define MAX_PAD  (NSLOT + N_EXPERTS*128)     /* 9216 */
#define MTILES   (MAX_PAD/128)               /* 72 */
#define LDS      72                           /* smem row stride in halves */

/* ------------------------------------------------------------------ */
/* device scratch (static: no allocation allowed)                      */
/* ------------------------------------------------------------------ */
__device__ int    g_idx[MAX_PAD];
__device__ int    g_slotpos[NSLOT];
__device__ int    g_counts[N_EXPERTS];
__device__ int    g_fill[N_EXPERTS];
__device__ int    g_padOff[N_EXPERTS + 1];
__device__ int    g_is64;
__device__ __half g_H[(size_t)MAX_PAD * INTER];   /* 37.75 MB fp16 hidden  */
__device__ float  g_O[(size_t)MAX_PAD * HIDDEN];  /* 37.75 MB per-slot out */

/* ------------------------------------------------------------------ */
/* helpers                                                             */
/* ------------------------------------------------------------------ */
static __device__ __forceinline__ uint32_t smem_u32(const void* p) {
    uint32_t a;
    asm("{ .reg .u64 t; cvta.to.shared.u64 t, %1; cvt.u32.u64 %0, t; }"
        : "=r"(a) : "l"(p));
    return a;
}
static __device__ __forceinline__ uint32_t h2u(__half2 h) {
    return *reinterpret_cast<uint32_t*>(&h);
}
static __device__ __forceinline__ void ldsm_x4(uint32_t* r, uint32_t addr) {
    asm volatile("ldmatrix.sync.aligned.m8n8.x4.shared.b16 {%0,%1,%2,%3}, [%4];"
                 : "=r"(r[0]), "=r"(r[1]), "=r"(r[2]), "=r"(r[3]) : "r"(addr));
}
static __device__ __forceinline__ void ldsm_x4_t(uint32_t* r, uint32_t addr) {
    asm volatile("ldmatrix.sync.aligned.m8n8.x4.trans.shared.b16 {%0,%1,%2,%3}, [%4];"
                 : "=r"(r[0]), "=r"(r[1]), "=r"(r[2]), "=r"(r[3]) : "r"(addr));
}
static __device__ __forceinline__ void mma16816(float* c, const uint32_t* a,
                                                const uint32_t* b) {
    asm volatile(
        "mma.sync.aligned.m16n8k16.row.col.f32.f16.f16.f32 "
        "{%0,%1,%2,%3}, {%4,%5,%6,%7}, {%8,%9}, {%0,%1,%2,%3};"
        : "+f"(c[0]), "+f"(c[1]), "+f"(c[2]), "+f"(c[3])
        : "r"(a[0]), "r"(a[1]), "r"(a[2]), "r"(a[3]), "r"(b[0]), "r"(b[1]));
}

/* ------------------------------------------------------------------ */
/* routing kernels                                                     */
/* ------------------------------------------------------------------ */
__global__ void k_init() {
    int i = blockIdx.x * blockDim.x + threadIdx.x;
    if (i < MAX_PAD) g_idx[i] = 0;
    if (i < N_EXPERTS) { g_counts[i] = 0; g_fill[i] = 0; }
    if (i == 0) g_is64 = 1;
}

/* expert_indices may land as int32 or int64 (jax x64). If int64 (LE),
   the high word of every value is 0. */
__global__ void k_detect(const int* __restrict__ ei) {
    int i = blockIdx.x * blockDim.x + threadIdx.x;
    if (i < NSLOT / 2) {
        if (ei[2 * i + 1] != 0) g_is64 = 0;
    }
}

__global__ void k_count(const int* __restrict__ ei) {
    int i = blockIdx.x * blockDim.x + threadIdx.x;
    if (i < NSLOT) {
        int e = g_is64 ? ei[2 * i] : ei[i];
        atomicAdd(&g_counts[e], 1);
    }
}

__global__ void k_scan() {
    if (threadIdx.x == 0) {
        int off = 0;
        for (int e = 0; e < N_EXPERTS; e++) {
            g_padOff[e] = off;
            off += (g_counts[e] + 127) & ~127;
        }
        g_padOff[N_EXPERTS] = off;
    }
}

__global__ void k_scatter(const int* __restrict__ ei) {
    int i = blockIdx.x * blockDim.x + threadIdx.x;
    if (i < NSLOT) {
        int e = g_is64 ? ei[2 * i] : ei[i];
        int pos = g_padOff[e] + atomicAdd(&g_fill[e], 1);
        g_idx[pos] = i >> 1;    /* token id */
        g_slotpos[i] = pos;     /* inverse map for combine */
    }
}

/* ------------------------------------------------------------------ */
/* GEMM1: g_H[slot, i] = silu(X@Wg) * (X@Wu)                           */
/* grid (MTILES, INTER/64), 256 threads                                */
/* ------------------------------------------------------------------ */
__global__ void __launch_bounds__(256, 2)
k_gemm1(const float* __restrict__ tokens, const float* __restrict__ gw,
        const float* __restrict__ uw) {
    __shared__ __align__(16) __half sA[128 * LDS];
    __shared__ __align__(16) __half sBg[64 * LDS];
    __shared__ __align__(16) __half sBu[64 * LDS];
    __shared__ int sIdx[128];

    const int mstart = blockIdx.x * 128;
    if (mstart >= g_padOff[N_EXPERTS]) return;
    const int nb = blockIdx.y * 64;

    int e = 0;
#pragma unroll
    for (int q = 1; q < N_EXPERTS; q++)
        if (g_padOff[q] <= mstart) e = q;

    const int tid = threadIdx.x;
    const int lane = tid & 31, wid = tid >> 5;
    const int wm = wid >> 2, wn = wid & 3;

    if (tid < 128) sIdx[tid] = g_idx[mstart + tid];
    __syncthreads();

    const float* gp = gw + (size_t)e * HIDDEN * INTER + nb;
    const float* up = uw + (size_t)e * HIDDEN * INTER + nb;
    const uint32_t aBase = smem_u32(sA);
    const uint32_t gBase = smem_u32(sBg);
    const uint32_t uBase = smem_u32(sBu);

    float cG[4][2][4] = {}, cU[4][2][4] = {};

    for (int c = 0; c < HIDDEN / 64; c++) {
        /* A: gather 128 token rows x 64 k, fp32 -> fp16 */
#pragma unroll
        for (int t = tid; t < 128 * 16; t += 256) {
            int r = t >> 4, s = t & 15;
            const float4 v = *(const float4*)(tokens + (size_t)sIdx[r] * HIDDEN + c * 64 + s * 4);
            *(uint2*)&sA[r * LDS + s * 4] =
                make_uint2(h2u(__floats2half2_rn(v.x, v.y)),
                           h2u(__floats2half2_rn(v.z, v.w)));
        }
        /* B: 64 k-rows x 64 n for gate and up */
#pragma unroll
        for (int t = tid; t < 64 * 16; t += 256) {
            int r = t >> 4, s = t & 15;
            const size_t go = (size_t)(c * 64 + r) * INTER + s * 4;
            const float4 vg = *(const float4*)(gp + go);
            const float4 vu = *(const float4*)(up + go);
            *(uint2*)&sBg[r * LDS + s * 4] =
                make_uint2(h2u(__floats2half2_rn(vg.x, vg.y)),
                           h2u(__floats2half2_rn(vg.z, vg.w)));
            *(uint2*)&sBu[r * LDS + s * 4] =
                make_uint2(h2u(__floats2half2_rn(vu.x, vu.y)),
                           h2u(__floats2half2_rn(vu.z, vu.w)));
        }
        __syncthreads();

#pragma unroll
        for (int ks = 0; ks < 4; ks++) {
            const int k0 = ks * 16;
            uint32_t a[4][4];
#pragma unroll
            for (int mt = 0; mt < 4; mt++)
                ldsm_x4(a[mt], aBase +
                    ((wm * 64 + mt * 16 + (lane & 15)) * LDS + k0 + ((lane >> 4) << 3)) * 2);
            uint32_t bg[4], bu[4];
            const uint32_t boff =
                ((k0 + (lane & 15)) * LDS + wn * 16 + ((lane >> 4) << 3)) * 2;
            ldsm_x4_t(bg, gBase + boff);
            ldsm_x4_t(bu, uBase + boff);
#pragma unroll
            for (int mt = 0; mt < 4; mt++) {
#pragma unroll
                for (int nt = 0; nt < 2; nt++) {
                    mma16816(cG[mt][nt], a[mt], bg + 2 * nt);
                    mma16816(cU[mt][nt], a[mt], bu + 2 * nt);
                }
            }
        }
        __syncthreads();
    }

    /* epilogue: silu(G) * U -> fp16 g_H */
    const int rbase = mstart + wm * 64 + (lane >> 2);
    const int cbase = nb + wn * 16 + (lane & 3) * 2;
#pragma unroll
    for (int mt = 0; mt < 4; mt++) {
#pragma unroll
        for (int nt = 0; nt < 2; nt++) {
#pragma unroll
            for (int hh = 0; hh < 2; hh++) {
                float g0 = cG[mt][nt][hh * 2], g1 = cG[mt][nt][hh * 2 + 1];
                float u0 = cU[mt][nt][hh * 2], u1 = cU[mt][nt][hh * 2 + 1];
                float h0 = g0 * u0 / (1.0f + __expf(-g0));
                float h1 = g1 * u1 / (1.0f + __expf(-g1));
                const int slot = rbase + mt * 16 + hh * 8;
                *(__half2*)&g_H[(size_t)slot * INTER + cbase + nt * 8] =
                    __floats2half2_rn(h0, h1);
            }
        }
    }
}

/* ------------------------------------------------------------------ */
/* GEMM2: g_O[slot, h] = H[slot] @ Wd                                  */
/* grid (MTILES, HIDDEN/64), 256 threads                               */
/* ------------------------------------------------------------------ */
__global__ void __launch_bounds__(256, 2)
k_gemm2(const float* __restrict__ dw) {
    __shared__ __align__(16) __half sA[128 * LDS];
    __shared__ __align__(16) __half sB[64 * LDS];

    const int mstart = blockIdx.x * 128;
    if (mstart >= g_padOff[N_EXPERTS]) return;
    const int nb = blockIdx.y * 64;

    int e = 0;
#pragma unroll
    for (int q = 1; q < N_EXPERTS; q++)
        if (g_padOff[q] <= mstart) e = q;

    const int tid = threadIdx.x;
    const int lane = tid & 31, wid = tid >> 5;
    const int wm = wid >> 2, wn = wid & 3;

    const float* dp = dw + (size_t)e * INTER * HIDDEN + nb;
    const uint32_t aBase = smem_u32(sA);
    const uint32_t bBase = smem_u32(sB);

    float cD[4][2][4] = {};

    for (int c = 0; c < INTER / 64; c++) {
        /* A: 128 hidden rows x 64 k (already fp16) */
#pragma unroll
        for (int t = tid; t < 128 * 8; t += 256) {
            int r = t >> 3, s = t & 7;
            const uint4 v = *(const uint4*)(g_H + (size_t)(mstart + r) * INTER + c * 64 + s * 8);
            *(uint4*)&sA[r * LDS + s * 8] = v;
        }
        /* B: 64 k-rows x 64 n of down weight */
#pragma unroll
        for (int t = tid; t < 64 * 16; t += 256) {
            int r = t >> 4, s = t & 15;
            const float4 vd = *(const float4*)(dp + (size_t)(c * 64 + r) * HIDDEN + s * 4);
            *(uint2*)&sB[r * LDS + s * 4] =
                make_uint2(h2u(__floats2half2_rn(vd.x, vd.y)),
                           h2u(__floats2half2_rn(vd.z, vd.w)));
        }
        __syncthreads();

#pragma unroll
        for (int ks = 0; ks < 4; ks++) {
            const int k0 = ks * 16;
            uint32_t a[4][4];
#pragma unroll
            for (int mt = 0; mt < 4; mt++)
                ldsm_x4(a[mt], aBase +
                    ((wm * 64 + mt * 16 + (lane & 15)) * LDS + k0 + ((lane >> 4) << 3)) * 2);
            uint32_t b[4];
            ldsm_x4_t(b, bBase +
                ((k0 + (lane & 15)) * LDS + wn * 16 + ((lane >> 4) << 3)) * 2);
#pragma unroll
            for (int mt = 0; mt < 4; mt++) {
#pragma unroll
                for (int nt = 0; nt < 2; nt++)
                    mma16816(cD[mt][nt], a[mt], b + 2 * nt);
            }
        }
        __syncthreads();
    }

    /* epilogue: plain fp32 stores to per-slot buffer (no atomics) */
    const int rbase = mstart + wm * 64 + (lane >> 2);
    const int cbase = nb + wn * 16 + (lane & 3) * 2;
#pragma unroll
    for (int mt = 0; mt < 4; mt++) {
#pragma unroll
        for (int nt = 0; nt < 2; nt++) {
#pragma unroll
            for (int hh = 0; hh < 2; hh++) {
                const int slot = rbase + mt * 16 + hh * 8;
                *(float2*)&g_O[(size_t)slot * HIDDEN + cbase + nt * 8] =
                    make_float2(cD[mt][nt][hh * 2], cD[mt][nt][hh * 2 + 1]);
            }
        }
    }
}

/* ------------------------------------------------------------------ */
/* combine: out[n] = ew[n,0]*g_O[pos(n,0)] + ew[n,1]*g_O[pos(n,1)]     */
/* ------------------------------------------------------------------ */
__global__ void k_combine(const float* __restrict__ ew, float* __restrict__ out) {
    int i = blockIdx.x * blockDim.x + threadIdx.x;
    if (i >= N_TOKENS * HIDDEN / 4) return;
    const int n = i / (HIDDEN / 4);
    const int h4 = (i % (HIDDEN / 4)) * 4;
    const int p0 = g_slotpos[2 * n], p1 = g_slotpos[2 * n + 1];
    const float w0 = ew[2 * n], w1 = ew[2 * n + 1];
    const float4 a = *(const float4*)&g_O[(size_t)p0 * HIDDEN + h4];
    const float4 b = *(const float4*)&g_O[(size_t)p1 * HIDDEN + h4];
    float4 o;
    o.x = w0 * a.x + w1 * b.x;
    o.y = w0 * a.y + w1 * b.y;
    o.z = w0 * a.z + w1 * b.z;
    o.w = w0 * a.w + w1 * b.w;
    ((float4*)out)[i] = o;
}

/* ------------------------------------------------------------------ */
extern "C" void kernel_launch(void* const* d_in, const int* in_sizes, int n_in,
                              void* d_out, int out_size) {
    const float* tokens = (const float*)d_in[0];
    const int*   ei     = (const int*)d_in[1];
    const float* ew     = (const float*)d_in[2];
    const float* gw     = (const float*)d_in[3];
    const float* uw     = (const float*)d_in[4];
    const float* dw     = (const float*)d_in[5];
    float* out = (float*)d_out;
    (void)in_sizes; (void)n_in; (void)out_size;

    k_init<<<(MAX_PAD + 255) / 256, 256>>>();
    k_detect<<<(NSLOT / 2 + 255) / 256, 256>>>(ei);
    k_count<<<(NSLOT + 255) / 256, 256>>>(ei);
    k_scan<<<1, 32>>>();
    k_scatter<<<(NSLOT + 255) / 256, 256>>>(ei);

    k_gemm1<<<dim3(MTILES, INTER / 64), 256>>>(tokens, gw, uw);
    k_gemm2<<<dim3(MTILES, HIDDEN / 64), 256>>>(dw);
    k_combine<<<(N_TOKENS * HIDDEN / 4 + 255) / 256, 256>>>(ew, out);
}

// round 4
// speedup vs baseline: 1.3245x; 1.3245x over previous
#include <cuda_runtime.h>
#include <cuda_fp16.h>
#include <cstdint>

#define N_TOKENS 4096
#define TOP_K    2
#define N_EXPERTS 8
#define HIDDEN   1024
#define INTER    2048
#define NSLOT    (N_TOKENS*TOP_K)            /* 8192 */
#define MAX_PAD  (NSLOT + N_EXPERTS*128)     /* 9216 */
#define MTILES   (MAX_PAD/128)               /* 72 */

#define KC   32        /* K-chunk per pipeline stage            */
#define LDA  40        /* A smem row stride (halves): 32 + 8 pad */
#define LDB  72        /* B smem row stride (halves): 64 + 8 pad */

/* ------------------------------------------------------------------ */
/* device scratch (static: no allocation allowed)                      */
/* ------------------------------------------------------------------ */
__device__ int    g_idx[MAX_PAD];
__device__ int    g_slotpos[NSLOT];
__device__ int    g_counts[N_EXPERTS];
__device__ int    g_fill[N_EXPERTS];
__device__ int    g_padOff[N_EXPERTS + 1];
__device__ int    g_is64;
__device__ __half g_A[(size_t)MAX_PAD * HIDDEN];            /* 18.9 MB gathered fp16 tokens */
__device__ __half g_H[(size_t)MAX_PAD * INTER];             /* 37.75 MB fp16 hidden  */
__device__ float  g_O[(size_t)MAX_PAD * HIDDEN];            /* 37.75 MB per-slot out */
__device__ __half g_Wg[(size_t)N_EXPERTS * HIDDEN * INTER]; /* 33.6 MB fp16 gate W   */
__device__ __half g_Wu[(size_t)N_EXPERTS * HIDDEN * INTER]; /* 33.6 MB fp16 up W     */
__device__ __half g_Wd[(size_t)N_EXPERTS * INTER * HIDDEN]; /* 33.6 MB fp16 down W   */

/* ------------------------------------------------------------------ */
/* helpers                                                             */
/* ------------------------------------------------------------------ */
static __device__ __forceinline__ uint32_t smem_u32(const void* p) {
    uint32_t a;
    asm("{ .reg .u64 t; cvta.to.shared.u64 t, %1; cvt.u32.u64 %0, t; }"
        : "=r"(a) : "l"(p));
    return a;
}
static __device__ __forceinline__ uint32_t h2u(__half2 h) {
    return *reinterpret_cast<uint32_t*>(&h);
}
static __device__ __forceinline__ void cp16(uint32_t dst, const void* src) {
    asm volatile("cp.async.cg.shared.global [%0], [%1], 16;"
                 :: "r"(dst), "l"(src) : "memory");
}
#define CP_COMMIT() asm volatile("cp.async.commit_group;" ::: "memory")
#define CP_WAIT(n)  asm volatile("cp.async.wait_group %0;" :: "n"(n) : "memory")

static __device__ __forceinline__ void ldsm_x4(uint32_t* r, uint32_t addr) {
    asm volatile("ldmatrix.sync.aligned.m8n8.x4.shared.b16 {%0,%1,%2,%3}, [%4];"
                 : "=r"(r[0]), "=r"(r[1]), "=r"(r[2]), "=r"(r[3]) : "r"(addr));
}
static __device__ __forceinline__ void ldsm_x4_t(uint32_t* r, uint32_t addr) {
    asm volatile("ldmatrix.sync.aligned.m8n8.x4.trans.shared.b16 {%0,%1,%2,%3}, [%4];"
                 : "=r"(r[0]), "=r"(r[1]), "=r"(r[2]), "=r"(r[3]) : "r"(addr));
}
static __device__ __forceinline__ void mma16816(float* c, const uint32_t* a,
                                                const uint32_t* b) {
    asm volatile(
        "mma.sync.aligned.m16n8k16.row.col.f32.f16.f16.f32 "
        "{%0,%1,%2,%3}, {%4,%5,%6,%7}, {%8,%9}, {%0,%1,%2,%3};"
        : "+f"(c[0]), "+f"(c[1]), "+f"(c[2]), "+f"(c[3])
        : "r"(a[0]), "r"(a[1]), "r"(a[2]), "r"(a[3]), "r"(b[0]), "r"(b[1]));
}

/* ------------------------------------------------------------------ */
/* routing kernels                                                     */
/* ------------------------------------------------------------------ */
__global__ void k_init() {
    int i = blockIdx.x * blockDim.x + threadIdx.x;
    if (i < MAX_PAD) g_idx[i] = 0;
    if (i < N_EXPERTS) { g_counts[i] = 0; g_fill[i] = 0; }
    if (i == 0) g_is64 = 1;
}

/* expert_indices may land as int32 or int64 (jax x64). If int64 (LE),
   the high word of every value is 0. */
__global__ void k_detect(const int* __restrict__ ei) {
    int i = blockIdx.x * blockDim.x + threadIdx.x;
    if (i < NSLOT / 2) {
        if (ei[2 * i + 1] != 0) g_is64 = 0;
    }
}

__global__ void k_count(const int* __restrict__ ei) {
    int i = blockIdx.x * blockDim.x + threadIdx.x;
    if (i < NSLOT) {
        int e = g_is64 ? ei[2 * i] : ei[i];
        atomicAdd(&g_counts[e], 1);
    }
}

__global__ void k_scan() {
    if (threadIdx.x == 0) {
        int off = 0;
        for (int e = 0; e < N_EXPERTS; e++) {
            g_padOff[e] = off;
            off += (g_counts[e] + 127) & ~127;
        }
        g_padOff[N_EXPERTS] = off;
    }
}

__global__ void k_scatter(const int* __restrict__ ei) {
    int i = blockIdx.x * blockDim.x + threadIdx.x;
    if (i < NSLOT) {
        int e = g_is64 ? ei[2 * i] : ei[i];
        int pos = g_padOff[e] + atomicAdd(&g_fill[e], 1);
        g_idx[pos] = i >> 1;    /* token id */
        g_slotpos[i] = pos;     /* inverse map for combine */
    }
}

/* fp32 -> fp16 weight convert: n4 float4 elements */
__global__ void k_cvt(const float4* __restrict__ src, uint2* __restrict__ dst, int n4) {
    int i = blockIdx.x * blockDim.x + threadIdx.x;
    if (i < n4) {
        float4 v = src[i];
        dst[i] = make_uint2(h2u(__floats2half2_rn(v.x, v.y)),
                            h2u(__floats2half2_rn(v.z, v.w)));
    }
}

/* gather token rows into padded fp16 slot matrix g_A */
__global__ void k_gather(const float* __restrict__ tokens) {
    int i = blockIdx.x * blockDim.x + threadIdx.x;   /* one float4 per thread */
    if (i >= MAX_PAD * (HIDDEN / 4)) return;
    const int slot = i / (HIDDEN / 4);
    const int h4 = (i % (HIDDEN / 4)) * 4;
    const float4 v = *(const float4*)(tokens + (size_t)g_idx[slot] * HIDDEN + h4);
    *(uint2*)(g_A + (size_t)slot * HIDDEN + h4) =
        make_uint2(h2u(__floats2half2_rn(v.x, v.y)),
                   h2u(__floats2half2_rn(v.z, v.w)));
}

/* ------------------------------------------------------------------ */
/* GEMM1: g_H[slot, i] = silu(X@Wg) * (X@Wu)                           */
/* grid (MTILES, INTER/64), 256 threads, 2-stage cp.async pipeline     */
/* ------------------------------------------------------------------ */
__global__ void __launch_bounds__(256, 2)
k_gemm1() {
    __shared__ __align__(16) __half sA[2][128 * LDA];  /* 2 x 10 KB  */
    __shared__ __align__(16) __half sBg[2][KC * LDB];  /* 2 x 4.5 KB */
    __shared__ __align__(16) __half sBu[2][KC * LDB];

    const int mstart = blockIdx.x * 128;
    if (mstart >= g_padOff[N_EXPERTS]) return;
    const int nb = blockIdx.y * 64;

    int e = 0;
#pragma unroll
    for (int q = 1; q < N_EXPERTS; q++)
        if (g_padOff[q] <= mstart) e = q;

    const int tid = threadIdx.x;
    const int lane = tid & 31, wid = tid >> 5;
    const int wm = wid >> 2, wn = wid & 3;

    const __half* gp = g_Wg + (size_t)e * HIDDEN * INTER + nb;
    const __half* up = g_Wu + (size_t)e * HIDDEN * INTER + nb;
    const __half* ap = g_A + (size_t)mstart * HIDDEN;

    uint32_t aSm[2], gSm[2], uSm[2];
#pragma unroll
    for (int s = 0; s < 2; s++) {
        aSm[s] = smem_u32(sA[s]);
        gSm[s] = smem_u32(sBg[s]);
        uSm[s] = smem_u32(sBu[s]);
    }

    /* per-thread load coordinates */
    const int ar = tid >> 2, as = tid & 3;      /* A: 2 iters of (r, 16B chunk) */
    const int br = tid >> 3, bs = tid & 7;      /* B: 1 iter                    */

    float cG[4][2][4] = {}, cU[4][2][4] = {};

    const int C = HIDDEN / KC;                  /* 32 chunks */

#define G1_LOAD(st, c) do {                                                   \
        const int k0 = (c) * KC;                                              \
        cp16(aSm[st] + (ar * LDA + as * 8) * 2,                               \
             ap + (size_t)ar * HIDDEN + k0 + as * 8);                         \
        cp16(aSm[st] + ((ar + 64) * LDA + as * 8) * 2,                        \
             ap + (size_t)(ar + 64) * HIDDEN + k0 + as * 8);                  \
        cp16(gSm[st] + (br * LDB + bs * 8) * 2,                               \
             gp + (size_t)(k0 + br) * INTER + bs * 8);                        \
        cp16(uSm[st] + (br * LDB + bs * 8) * 2,                               \
             up + (size_t)(k0 + br) * INTER + bs * 8);                        \
        CP_COMMIT();                                                          \
    } while (0)

    G1_LOAD(0, 0);

    for (int c = 0; c < C; c++) {
        const int st = c & 1;
        if (c + 1 < C) {
            G1_LOAD(st ^ 1, c + 1);
            CP_WAIT(1);
        } else {
            CP_WAIT(0);
        }
        __syncthreads();

#pragma unroll
        for (int ks = 0; ks < 2; ks++) {
            const int k0 = ks * 16;
            uint32_t a[4][4];
#pragma unroll
            for (int mt = 0; mt < 4; mt++)
                ldsm_x4(a[mt], aSm[st] +
                    ((wm * 64 + mt * 16 + (lane & 15)) * LDA + k0 + ((lane >> 4) << 3)) * 2);
            uint32_t bg[4], bu[4];
            const uint32_t boff =
                ((k0 + (lane & 15)) * LDB + wn * 16 + ((lane >> 4) << 3)) * 2;
            ldsm_x4_t(bg, gSm[st] + boff);
            ldsm_x4_t(bu, uSm[st] + boff);
#pragma unroll
            for (int mt = 0; mt < 4; mt++) {
#pragma unroll
                for (int nt = 0; nt < 2; nt++) {
                    mma16816(cG[mt][nt], a[mt], bg + 2 * nt);
                    mma16816(cU[mt][nt], a[mt], bu + 2 * nt);
                }
            }
        }
        if (c + 1 < C) __syncthreads();
    }

    /* epilogue: silu(G) * U -> fp16 g_H */
    const int rbase = mstart + wm * 64 + (lane >> 2);
    const int cbase = nb + wn * 16 + (lane & 3) * 2;
#pragma unroll
    for (int mt = 0; mt < 4; mt++) {
#pragma unroll
        for (int nt = 0; nt < 2; nt++) {
#pragma unroll
            for (int hh = 0; hh < 2; hh++) {
                float g0 = cG[mt][nt][hh * 2], g1 = cG[mt][nt][hh * 2 + 1];
                float u0 = cU[mt][nt][hh * 2], u1 = cU[mt][nt][hh * 2 + 1];
                float h0 = g0 * u0 / (1.0f + __expf(-g0));
                float h1 = g1 * u1 / (1.0f + __expf(-g1));
                const int slot = rbase + mt * 16 + hh * 8;
                *(__half2*)&g_H[(size_t)slot * INTER + cbase + nt * 8] =
                    __floats2half2_rn(h0, h1);
            }
        }
    }
}

/* ------------------------------------------------------------------ */
/* GEMM2: g_O[slot, h] = H[slot] @ Wd                                  */
/* grid (MTILES, HIDDEN/64), 256 threads, 2-stage cp.async pipeline    */
/* ------------------------------------------------------------------ */
__global__ void __launch_bounds__(256, 2)
k_gemm2() {
    __shared__ __align__(16) __half sA[2][128 * LDA];
    __shared__ __align__(16) __half sB[2][KC * LDB];

    const int mstart = blockIdx.x * 128;
    if (mstart >= g_padOff[N_EXPERTS]) return;
    const int nb = blockIdx.y * 64;

    int e = 0;
#pragma unroll
    for (int q = 1; q < N_EXPERTS; q++)
        if (g_padOff[q] <= mstart) e = q;

    const int tid = threadIdx.x;
    const int lane = tid & 31, wid = tid >> 5;
    const int wm = wid >> 2, wn = wid & 3;

    const __half* dp = g_Wd + (size_t)e * INTER * HIDDEN + nb;
    const __half* ap = g_H + (size_t)mstart * INTER;

    uint32_t aSm[2], bSm[2];
#pragma unroll
    for (int s = 0; s < 2; s++) {
        aSm[s] = smem_u32(sA[s]);
        bSm[s] = smem_u32(sB[s]);
    }

    const int ar = tid >> 2, as = tid & 3;
    const int br = tid >> 3, bs = tid & 7;

    float cD[4][2][4] = {};

    const int C = INTER / KC;                   /* 64 chunks */

#define G2_LOAD(st, c) do {                                                   \
        const int k0 = (c) * KC;                                              \
        cp16(aSm[st] + (ar * LDA + as * 8) * 2,                               \
             ap + (size_t)ar * INTER + k0 + as * 8);                          \
        cp16(aSm[st] + ((ar + 64) * LDA + as * 8) * 2,                        \
             ap + (size_t)(ar + 64) * INTER + k0 + as * 8);                   \
        cp16(bSm[st] + (br * LDB + bs * 8) * 2,                               \
             dp + (size_t)(k0 + br) * HIDDEN + bs * 8);                       \
        CP_COMMIT();                                                          \
    } while (0)

    G2_LOAD(0, 0);

    for (int c = 0; c < C; c++) {
        const int st = c & 1;
        if (c + 1 < C) {
            G2_LOAD(st ^ 1, c + 1);
            CP_WAIT(1);
        } else {
            CP_WAIT(0);
        }
        __syncthreads();

#pragma unroll
        for (int ks = 0; ks < 2; ks++) {
            const int k0 = ks * 16;
            uint32_t a[4][4];
#pragma unroll
            for (int mt = 0; mt < 4; mt++)
                ldsm_x4(a[mt], aSm[st] +
                    ((wm * 64 + mt * 16 + (lane & 15)) * LDA + k0 + ((lane >> 4) << 3)) * 2);
            uint32_t b[4];
            ldsm_x4_t(b, bSm[st] +
                ((k0 + (lane & 15)) * LDB + wn * 16 + ((lane >> 4) << 3)) * 2);
#pragma unroll
            for (int mt = 0; mt < 4; mt++) {
#pragma unroll
                for (int nt = 0; nt < 2; nt++)
                    mma16816(cD[mt][nt], a[mt], b + 2 * nt);
            }
        }
        if (c + 1 < C) __syncthreads();
    }

    /* epilogue: plain fp32 stores to per-slot buffer (no atomics) */
    const int rbase = mstart + wm * 64 + (lane >> 2);
    const int cbase = nb + wn * 16 + (lane & 3) * 2;
#pragma unroll
    for (int mt = 0; mt < 4; mt++) {
#pragma unroll
        for (int nt = 0; nt < 2; nt++) {
#pragma unroll
            for (int hh = 0; hh < 2; hh++) {
                const int slot = rbase + mt * 16 + hh * 8;
                *(float2*)&g_O[(size_t)slot * HIDDEN + cbase + nt * 8] =
                    make_float2(cD[mt][nt][hh * 2], cD[mt][nt][hh * 2 + 1]);
            }
        }
    }
}

/* ------------------------------------------------------------------ */
/* combine: out[n] = ew[n,0]*g_O[pos(n,0)] + ew[n,1]*g_O[pos(n,1)]     */
/* ------------------------------------------------------------------ */
__global__ void k_combine(const float* __restrict__ ew, float* __restrict__ out) {
    int i = blockIdx.x * blockDim.x + threadIdx.x;
    if (i >= N_TOKENS * HIDDEN / 4) return;
    const int n = i / (HIDDEN / 4);
    const int h4 = (i % (HIDDEN / 4)) * 4;
    const int p0 = g_slotpos[2 * n], p1 = g_slotpos[2 * n + 1];
    const float w0 = ew[2 * n], w1 = ew[2 * n + 1];
    const float4 a = *(const float4*)&g_O[(size_t)p0 * HIDDEN + h4];
    const float4 b = *(const float4*)&g_O[(size_t)p1 * HIDDEN + h4];
    float4 o;
    o.x = w0 * a.x + w1 * b.x;
    o.y = w0 * a.y + w1 * b.y;
    o.z = w0 * a.z + w1 * b.z;
    o.w = w0 * a.w + w1 * b.w;
    ((float4*)out)[i] = o;
}

/* ------------------------------------------------------------------ */
extern "C" void kernel_launch(void* const* d_in, const int* in_sizes, int n_in,
                              void* d_out, int out_size) {
    const float* tokens = (const float*)d_in[0];
    const int*   ei     = (const int*)d_in[1];
    const float* ew     = (const float*)d_in[2];
    const float* gw     = (const float*)d_in[3];
    const float* uw     = (const float*)d_in[4];
    const float* dw     = (const float*)d_in[5];
    float* out = (float*)d_out;
    (void)in_sizes; (void)n_in; (void)out_size;

    const int W4 = N_EXPERTS * HIDDEN * INTER / 4;   /* float4 count per weight */
    __half *wg, *wu, *wd;
    cudaGetSymbolAddress((void**)&wg, g_Wg);
    cudaGetSymbolAddress((void**)&wu, g_Wu);
    cudaGetSymbolAddress((void**)&wd, g_Wd);

    k_init<<<(MAX_PAD + 255) / 256, 256>>>();
    k_detect<<<(NSLOT / 2 + 255) / 256, 256>>>(ei);
    k_count<<<(NSLOT + 255) / 256, 256>>>(ei);
    k_scan<<<1, 32>>>();
    k_scatter<<<(NSLOT + 255) / 256, 256>>>(ei);

    k_cvt<<<(W4 + 255) / 256, 256>>>((const float4*)gw, (uint2*)wg, W4);
    k_cvt<<<(W4 + 255) / 256, 256>>>((const float4*)uw, (uint2*)wu, W4);
    k_cvt<<<(W4 + 255) / 256, 256>>>((const float4*)dw, (uint2*)wd, W4);
    k_gather<<<(MAX_PAD * (HIDDEN / 4) + 255) / 256, 256>>>(tokens);

    k_gemm1<<<dim3(MTILES, INTER / 64), 256>>>();
    k_gemm2<<<dim3(MTILES, HIDDEN / 64), 256>>>();
    k_combine<<<(N_TOKENS * HIDDEN / 4 + 255) / 256, 256>>>(ew, out);
}

// round 6
// speedup vs baseline: 1.4688x; 1.1089x over previous
#include <cuda_runtime.h>
#include <cuda_fp16.h>
#include <cstdint>

#define N_TOKENS 4096
#define TOP_K    2
#define N_EXPERTS 8
#define HIDDEN   1024
#define INTER    2048
#define NSLOT    (N_TOKENS*TOP_K)            /* 8192 */
#define MAX_PAD  (NSLOT + N_EXPERTS*128)     /* 9216 */
#define MTILES   (MAX_PAD/128)               /* 72 */

#define KC    32       /* K-chunk per pipeline stage             */
#define LDA   40       /* A smem row stride (halves): 32 + 8 pad */
#define LDB   72       /* B smem row stride (halves, 64-wide)    */
#define LDB2  136      /* B smem row stride (halves, 128-wide)   */

/* gemm1 stage layout (halves): A | Bg | Bu */
#define G1_A    0
#define G1_BG   (128*LDA)                     /* 5120 */
#define G1_BU   (G1_BG + KC*LDB)              /* 7424 */
#define G1_ST   (G1_BU + KC*LDB)              /* 9728 halves = 19456 B */
#define G1_SMEM (3*G1_ST*2)                   /* 58368 B */

/* gemm2 stage layout (halves): A | B */
#define G2_A    0
#define G2_B    (128*LDA)                     /* 5120 */
#define G2_ST   (G2_B + KC*LDB2)              /* 9472 halves = 18944 B */
#define G2_SMEM (3*G2_ST*2)                   /* 56832 B */

/* ------------------------------------------------------------------ */
/* device scratch (static: no allocation allowed)                      */
/* ------------------------------------------------------------------ */
__device__ int    g_idx[MAX_PAD];
__device__ int    g_slotpos[NSLOT];
__device__ int    g_padOff[N_EXPERTS + 1];
__device__ __half g_A[(size_t)MAX_PAD * HIDDEN];            /* gathered fp16 tokens */
__device__ __half g_H[(size_t)MAX_PAD * INTER];             /* fp16 hidden          */
__device__ float  g_O[(size_t)MAX_PAD * HIDDEN];            /* per-slot out         */
__device__ __half g_Wg[(size_t)N_EXPERTS * HIDDEN * INTER];
__device__ __half g_Wu[(size_t)N_EXPERTS * HIDDEN * INTER];
__device__ __half g_Wd[(size_t)N_EXPERTS * INTER * HIDDEN];

/* ------------------------------------------------------------------ */
/* helpers                                                             */
/* ------------------------------------------------------------------ */
static __device__ __forceinline__ uint32_t smem_u32(const void* p) {
    uint32_t a;
    asm("{ .reg .u64 t; cvta.to.shared.u64 t, %1; cvt.u32.u64 %0, t; }"
        : "=r"(a) : "l"(p));
    return a;
}
static __device__ __forceinline__ uint32_t h2u(__half2 h) {
    return *reinterpret_cast<uint32_t*>(&h);
}
static __device__ __forceinline__ void cp16(uint32_t dst, const void* src) {
    asm volatile("cp.async.cg.shared.global [%0], [%1], 16;"
                 :: "r"(dst), "l"(src) : "memory");
}
#define CP_COMMIT() asm volatile("cp.async.commit_group;" ::: "memory")
#define CP_WAIT1()  asm volatile("cp.async.wait_group 1;" ::: "memory")

static __device__ __forceinline__ void ldsm_x4(uint32_t* r, uint32_t addr) {
    asm volatile("ldmatrix.sync.aligned.m8n8.x4.shared.b16 {%0,%1,%2,%3}, [%4];"
                 : "=r"(r[0]), "=r"(r[1]), "=r"(r[2]), "=r"(r[3]) : "r"(addr));
}
static __device__ __forceinline__ void ldsm_x4_t(uint32_t* r, uint32_t addr) {
    asm volatile("ldmatrix.sync.aligned.m8n8.x4.trans.shared.b16 {%0,%1,%2,%3}, [%4];"
                 : "=r"(r[0]), "=r"(r[1]), "=r"(r[2]), "=r"(r[3]) : "r"(addr));
}
static __device__ __forceinline__ void mma16816(float* c, const uint32_t* a,
                                                const uint32_t* b) {
    asm volatile(
        "mma.sync.aligned.m16n8k16.row.col.f32.f16.f16.f32 "
        "{%0,%1,%2,%3}, {%4,%5,%6,%7}, {%8,%9}, {%0,%1,%2,%3};"
        : "+f"(c[0]), "+f"(c[1]), "+f"(c[2]), "+f"(c[3])
        : "r"(a[0]), "r"(a[1]), "r"(a[2]), "r"(a[3]), "r"(b[0]), "r"(b[1]));
}

/* ------------------------------------------------------------------ */
/* single-CTA routing: detect dtype, histogram, padded scan, scatter   */
/* ------------------------------------------------------------------ */
__global__ void k_route(const int* __restrict__ ei) {
    __shared__ int s_cnt[N_EXPERTS];
    __shared__ int s_off[N_EXPERTS + 1];
    __shared__ int s_fill[N_EXPERTS];
    const int tid = threadIdx.x;               /* 1024 threads */
    if (tid < N_EXPERTS) { s_cnt[tid] = 0; s_fill[tid] = 0; }
    for (int i = tid; i < MAX_PAD; i += 1024) g_idx[i] = 0;
    __syncthreads();

    /* int32 vs int64 expert_indices (jax x64): if int64 LE, all high words 0 */
    int bad = 0;
    for (int i = tid; i < NSLOT / 2; i += 1024)
        bad |= (ei[2 * i + 1] != 0);
    const int is64 = !__syncthreads_or(bad);

    /* warp-aggregated histogram */
    for (int i = tid; i < NSLOT; i += 1024) {
        const int e = is64 ? ei[2 * i] : ei[i];
        const unsigned m = __match_any_sync(0xffffffffu, e);
        if ((tid & 31) == __ffs(m) - 1)
            atomicAdd(&s_cnt[e], __popc(m));
    }
    __syncthreads();
    if (tid == 0) {
        int off = 0;
        for (int e = 0; e < N_EXPERTS; e++) {
            s_off[e] = off; g_padOff[e] = off;
            off += (s_cnt[e] + 127) & ~127;
        }
        s_off[N_EXPERTS] = off; g_padOff[N_EXPERTS] = off;
    }
    __syncthreads();

    /* warp-aggregated scatter */
    for (int i = tid; i < NSLOT; i += 1024) {
        const int e = is64 ? ei[2 * i] : ei[i];
        const unsigned m = __match_any_sync(0xffffffffu, e);
        const int leader = __ffs(m) - 1;
        const int rank = __popc(m & ((1u << (tid & 31)) - 1));
        int base = 0;
        if ((tid & 31) == leader) base = atomicAdd(&s_fill[e], __popc(m));
        base = __shfl_sync(0xffffffffu, base, leader);
        const int pos = s_off[e] + base + rank;
        g_idx[pos] = i >> 1;
        g_slotpos[i] = pos;
    }
}

/* fp32 -> fp16 convert for all three weight tensors in one launch */
#define W4 (N_EXPERTS * HIDDEN * INTER / 4)
__global__ void k_cvt3(const float4* __restrict__ g, const float4* __restrict__ u,
                       const float4* __restrict__ d, uint2* __restrict__ wg,
                       uint2* __restrict__ wu, uint2* __restrict__ wd) {
    int i = blockIdx.x * blockDim.x + threadIdx.x;
    if (i >= 3 * W4) return;
    const float4* src; uint2* dst; int j;
    if (i < W4)            { src = g; dst = wg; j = i; }
    else if (i < 2 * W4)   { src = u; dst = wu; j = i - W4; }
    else                   { src = d; dst = wd; j = i - 2 * W4; }
    float4 v = src[j];
    dst[j] = make_uint2(h2u(__floats2half2_rn(v.x, v.y)),
                        h2u(__floats2half2_rn(v.z, v.w)));
}

/* gather token rows into padded fp16 slot matrix g_A */
__global__ void k_gather(const float* __restrict__ tokens) {
    int i = blockIdx.x * blockDim.x + threadIdx.x;
    if (i >= MAX_PAD * (HIDDEN / 4)) return;
    const int slot = i / (HIDDEN / 4);
    const int h4 = (i % (HIDDEN / 4)) * 4;
    const float4 v = *(const float4*)(tokens + (size_t)g_idx[slot] * HIDDEN + h4);
    *(uint2*)(g_A + (size_t)slot * HIDDEN + h4) =
        make_uint2(h2u(__floats2half2_rn(v.x, v.y)),
                   h2u(__floats2half2_rn(v.z, v.w)));
}

/* ------------------------------------------------------------------ */
/* GEMM1: g_H = silu(X@Wg) * (X@Wu); tile 128m x 64n (G+U)             */
/* grid (MTILES, INTER/64), 256 thr, 3-stage cp.async                  */
/* race-free order: wait(1) -> sync -> prefetch(c+2) -> compute(c)     */
/* ------------------------------------------------------------------ */
__global__ void __launch_bounds__(256, 2)
k_gemm1() {
    extern __shared__ __half dsm[];

    const int mstart = blockIdx.x * 128;
    if (mstart >= g_padOff[N_EXPERTS]) return;
    const int nb = blockIdx.y * 64;

    int e = 0;
#pragma unroll
    for (int q = 1; q < N_EXPERTS; q++)
        if (g_padOff[q] <= mstart) e = q;

    const int tid = threadIdx.x;
    const int lane = tid & 31, wid = tid >> 5;
    const int wm = wid >> 2, wn = wid & 3;

    const __half* gp = g_Wg + (size_t)e * HIDDEN * INTER + nb;
    const __half* up = g_Wu + (size_t)e * HIDDEN * INTER + nb;
    const __half* ap = g_A + (size_t)mstart * HIDDEN;

    const uint32_t smBase = smem_u32(dsm);
    uint32_t stA[3], stG[3], stU[3];
#pragma unroll
    for (int s = 0; s < 3; s++) {
        stA[s] = smBase + (s * G1_ST + G1_A) * 2;
        stG[s] = smBase + (s * G1_ST + G1_BG) * 2;
        stU[s] = smBase + (s * G1_ST + G1_BU) * 2;
    }

    const int ar = tid >> 2, as = tid & 3;
    const int br = tid >> 3, bs = tid & 7;

    float cG[4][2][4] = {}, cU[4][2][4] = {};
    const int C = HIDDEN / KC;                  /* 32 */

#define G1_LOAD(s, c) do {                                                    \
        const int k0 = (c) * KC;                                              \
        cp16(stA[s] + (ar * LDA + as * 8) * 2,                                \
             ap + (size_t)ar * HIDDEN + k0 + as * 8);                         \
        cp16(stA[s] + ((ar + 64) * LDA + as * 8) * 2,                         \
             ap + (size_t)(ar + 64) * HIDDEN + k0 + as * 8);                  \
        cp16(stG[s] + (br * LDB + bs * 8) * 2,                                \
             gp + (size_t)(k0 + br) * INTER + bs * 8);                        \
        cp16(stU[s] + (br * LDB + bs * 8) * 2,                                \
             up + (size_t)(k0 + br) * INTER + bs * 8);                        \
    } while (0)

    G1_LOAD(0, 0); CP_COMMIT();
    G1_LOAD(1, 1); CP_COMMIT();

    int st = 0, nst = 2;
    for (int c = 0; c < C; c++) {
        CP_WAIT1();                 /* chunk c resident (≤1 pending group) */
        __syncthreads();            /* all warps done with stage nst       */
        if (c + 2 < C) G1_LOAD(nst, c + 2);
        CP_COMMIT();                /* unconditional: keeps group count aligned */

#pragma unroll
        for (int ks = 0; ks < 2; ks++) {
            const int k0 = ks * 16;
            uint32_t a[4][4];
#pragma unroll
            for (int mt = 0; mt < 4; mt++)
                ldsm_x4(a[mt], stA[st] +
                    ((wm * 64 + mt * 16 + (lane & 15)) * LDA + k0 + ((lane >> 4) << 3)) * 2);
            uint32_t bg[4], bu[4];
            const uint32_t boff =
                ((k0 + (lane & 15)) * LDB + wn * 16 + ((lane >> 4) << 3)) * 2;
            ldsm_x4_t(bg, stG[st] + boff);
            ldsm_x4_t(bu, stU[st] + boff);
#pragma unroll
            for (int mt = 0; mt < 4; mt++) {
#pragma unroll
                for (int nt = 0; nt < 2; nt++) {
                    mma16816(cG[mt][nt], a[mt], bg + 2 * nt);
                    mma16816(cU[mt][nt], a[mt], bu + 2 * nt);
                }
            }
        }
        st = (st == 2) ? 0 : st + 1;
        nst = (nst == 2) ? 0 : nst + 1;
    }

    /* epilogue: silu(G) * U -> fp16 g_H */
    const int rbase = mstart + wm * 64 + (lane >> 2);
    const int cbase = nb + wn * 16 + (lane & 3) * 2;
#pragma unroll
    for (int mt = 0; mt < 4; mt++) {
#pragma unroll
        for (int nt = 0; nt < 2; nt++) {
#pragma unroll
            for (int hh = 0; hh < 2; hh++) {
                float g0 = cG[mt][nt][hh * 2], g1 = cG[mt][nt][hh * 2 + 1];
                float u0 = cU[mt][nt][hh * 2], u1 = cU[mt][nt][hh * 2 + 1];
                float h0 = g0 * u0 / (1.0f + __expf(-g0));
                float h1 = g1 * u1 / (1.0f + __expf(-g1));
                const int slot = rbase + mt * 16 + hh * 8;
                *(__half2*)&g_H[(size_t)slot * INTER + cbase + nt * 8] =
                    __floats2half2_rn(h0, h1);
            }
        }
    }
}

/* ------------------------------------------------------------------ */
/* GEMM2: g_O = H @ Wd; tile 128m x 128n                               */
/* grid (MTILES, HIDDEN/128), 256 thr, 3-stage cp.async                */
/* ------------------------------------------------------------------ */
__global__ void __launch_bounds__(256, 2)
k_gemm2() {
    extern __shared__ __half dsm[];

    const int mstart = blockIdx.x * 128;
    if (mstart >= g_padOff[N_EXPERTS]) return;
    const int nb = blockIdx.y * 128;

    int e = 0;
#pragma unroll
    for (int q = 1; q < N_EXPERTS; q++)
        if (g_padOff[q] <= mstart) e = q;

    const int tid = threadIdx.x;
    const int lane = tid & 31, wid = tid >> 5;
    const int wm = wid >> 2, wn = wid & 3;    /* warp tile 64m x 32n */

    const __half* dp = g_Wd + (size_t)e * INTER * HIDDEN + nb;
    const __half* ap = g_H + (size_t)mstart * INTER;

    const uint32_t smBase = smem_u32(dsm);
    uint32_t stA[3], stB[3];
#pragma unroll
    for (int s = 0; s < 3; s++) {
        stA[s] = smBase + (s * G2_ST + G2_A) * 2;
        stB[s] = smBase + (s * G2_ST + G2_B) * 2;
    }

    const int ar = tid >> 2, as = tid & 3;
    const int br = tid >> 3, bs = tid & 7;

    float cD[4][4][4] = {};
    const int C = INTER / KC;                   /* 64 */

#define G2_LOAD(s, c) do {                                                    \
        const int k0 = (c) * KC;                                              \
        cp16(stA[s] + (ar * LDA + as * 8) * 2,                                \
             ap + (size_t)ar * INTER + k0 + as * 8);                          \
        cp16(stA[s] + ((ar + 64) * LDA + as * 8) * 2,                         \
             ap + (size_t)(ar + 64) * INTER + k0 + as * 8);                   \
        cp16(stB[s] + (br * LDB2 + bs * 8) * 2,                               \
             dp + (size_t)(k0 + br) * HIDDEN + bs * 8);                       \
        cp16(stB[s] + (br * LDB2 + 64 + bs * 8) * 2,                          \
             dp + (size_t)(k0 + br) * HIDDEN + 64 + bs * 8);                  \
    } while (0)

    G2_LOAD(0, 0); CP_COMMIT();
    G2_LOAD(1, 1); CP_COMMIT();

    int st = 0, nst = 2;
    for (int c = 0; c < C; c++) {
        CP_WAIT1();
        __syncthreads();
        if (c + 2 < C) G2_LOAD(nst, c + 2);
        CP_COMMIT();

#pragma unroll
        for (int ks = 0; ks < 2; ks++) {
            const int k0 = ks * 16;
            uint32_t a[4][4];
#pragma unroll
            for (int mt = 0; mt < 4; mt++)
                ldsm_x4(a[mt], stA[st] +
                    ((wm * 64 + mt * 16 + (lane & 15)) * LDA + k0 + ((lane >> 4) << 3)) * 2);
            uint32_t bb[2][4];
#pragma unroll
            for (int nn = 0; nn < 2; nn++)
                ldsm_x4_t(bb[nn], stB[st] +
                    ((k0 + (lane & 15)) * LDB2 + wn * 32 + nn * 16 + ((lane >> 4) << 3)) * 2);
#pragma unroll
            for (int mt = 0; mt < 4; mt++) {
#pragma unroll
                for (int nt = 0; nt < 4; nt++)
                    mma16816(cD[mt][nt], a[mt], bb[nt >> 1] + 2 * (nt & 1));
            }
        }
        st = (st == 2) ? 0 : st + 1;
        nst = (nst == 2) ? 0 : nst + 1;
    }

    /* epilogue: plain fp32 stores to per-slot buffer (no atomics) */
    const int rbase = mstart + wm * 64 + (lane >> 2);
    const int cbase = nb + wn * 32 + (lane & 3) * 2;
#pragma unroll
    for (int mt = 0; mt < 4; mt++) {
#pragma unroll
        for (int nt = 0; nt < 4; nt++) {
#pragma unroll
            for (int hh = 0; hh < 2; hh++) {
                const int slot = rbase + mt * 16 + hh * 8;
                *(float2*)&g_O[(size_t)slot * HIDDEN + cbase + nt * 8] =
                    make_float2(cD[mt][nt][hh * 2], cD[mt][nt][hh * 2 + 1]);
            }
        }
    }
}

/* ------------------------------------------------------------------ */
/* combine: out[n] = ew[n,0]*g_O[pos(n,0)] + ew[n,1]*g_O[pos(n,1)]     */
/* ------------------------------------------------------------------ */
__global__ void k_combine(const float* __restrict__ ew, float* __restrict__ out) {
    int i = blockIdx.x * blockDim.x + threadIdx.x;
    if (i >= N_TOKENS * HIDDEN / 4) return;
    const int n = i / (HIDDEN / 4);
    const int h4 = (i % (HIDDEN / 4)) * 4;
    const int p0 = g_slotpos[2 * n], p1 = g_slotpos[2 * n + 1];
    const float w0 = ew[2 * n], w1 = ew[2 * n + 1];
    const float4 a = *(const float4*)&g_O[(size_t)p0 * HIDDEN + h4];
    const float4 b = *(const float4*)&g_O[(size_t)p1 * HIDDEN + h4];
    float4 o;
    o.x = w0 * a.x + w1 * b.x;
    o.y = w0 * a.y + w1 * b.y;
    o.z = w0 * a.z + w1 * b.z;
    o.w = w0 * a.w + w1 * b.w;
    ((float4*)out)[i] = o;
}

/* ------------------------------------------------------------------ */
extern "C" void kernel_launch(void* const* d_in, const int* in_sizes, int n_in,
                              void* d_out, int out_size) {
    const float* tokens = (const float*)d_in[0];
    const int*   ei     = (const int*)d_in[1];
    const float* ew     = (const float*)d_in[2];
    const float* gw     = (const float*)d_in[3];
    const float* uw     = (const float*)d_in[4];
    const float* dw     = (const float*)d_in[5];
    float* out = (float*)d_out;
    (void)in_sizes; (void)n_in; (void)out_size;

    __half *wg, *wu, *wd;
    cudaGetSymbolAddress((void**)&wg, g_Wg);
    cudaGetSymbolAddress((void**)&wu, g_Wu);
    cudaGetSymbolAddress((void**)&wd, g_Wd);
    cudaFuncSetAttribute(k_gemm1, cudaFuncAttributeMaxDynamicSharedMemorySize, G1_SMEM);
    cudaFuncSetAttribute(k_gemm2, cudaFuncAttributeMaxDynamicSharedMemorySize, G2_SMEM);

    k_route<<<1, 1024>>>(ei);
    k_cvt3<<<(3 * W4 + 255) / 256, 256>>>((const float4*)gw, (const float4*)uw,
                                          (const float4*)dw, (uint2*)wg,
                                          (uint2*)wu, (uint2*)wd);
    k_gather<<<(MAX_PAD * (HIDDEN / 4) + 255) / 256, 256>>>(tokens);

    k_gemm1<<<dim3(MTILES, INTER / 64), 256, G1_SMEM>>>();
    k_gemm2<<<dim3(MTILES, HIDDEN / 128), 256, G2_SMEM>>>();
    k_combine<<<(N_TOKENS * HIDDEN / 4 + 255) / 256, 256>>>(ew, out);
}

// round 7
// speedup vs baseline: 1.5905x; 1.0829x over previous
#include <cuda_runtime.h>
#include <cuda_fp16.h>
#include <cstdint>

#define N_TOKENS 4096
#define TOP_K    2
#define N_EXPERTS 8
#define HIDDEN   1024
#define INTER    2048
#define NSLOT    (N_TOKENS*TOP_K)            /* 8192 */
#define MAX_PAD  (NSLOT + N_EXPERTS*128)     /* 9216 */
#define MTILES   (MAX_PAD/128)               /* 72 */

#define KC    64       /* K-chunk per pipeline stage             */
#define LDA   72       /* A smem row stride (halves): 64 + 8 pad */
#define LDB   72       /* B smem row stride (halves, 64-wide)    */
#define LDB2  136      /* B smem row stride (halves, 128-wide)   */

/* gemm1 stage layout (halves): A | Bg | Bu */
#define G1_A    0
#define G1_BG   (128*LDA)                     /* 9216  */
#define G1_BU   (G1_BG + KC*LDB)              /* 13824 */
#define G1_ST   (G1_BU + KC*LDB)              /* 18432 halves = 36864 B */
#define G1_SMEM (3*G1_ST*2)                   /* 110592 B */

/* gemm2 stage layout (halves): A | B */
#define G2_A    0
#define G2_B    (128*LDA)                     /* 9216 */
#define G2_ST   (G2_B + KC*LDB2)              /* 17920 halves = 35840 B */
#define G2_SMEM (3*G2_ST*2)                   /* 107520 B */

/* ------------------------------------------------------------------ */
/* device scratch (static: no allocation allowed)                      */
/* ------------------------------------------------------------------ */
__device__ int    g_idx[MAX_PAD];
__device__ int    g_slotpos[NSLOT];
__device__ int    g_padOff[N_EXPERTS + 1];
__device__ __half g_A[(size_t)MAX_PAD * HIDDEN];            /* gathered fp16 tokens */
__device__ __half g_H[(size_t)MAX_PAD * INTER];             /* fp16 hidden          */
__device__ float  g_O[(size_t)MAX_PAD * HIDDEN];            /* per-slot out         */
__device__ __half g_Wg[(size_t)N_EXPERTS * HIDDEN * INTER];
__device__ __half g_Wu[(size_t)N_EXPERTS * HIDDEN * INTER];
__device__ __half g_Wd[(size_t)N_EXPERTS * INTER * HIDDEN];

/* ------------------------------------------------------------------ */
/* helpers                                                             */
/* ------------------------------------------------------------------ */
static __device__ __forceinline__ uint32_t smem_u32(const void* p) {
    uint32_t a;
    asm("{ .reg .u64 t; cvta.to.shared.u64 t, %1; cvt.u32.u64 %0, t; }"
        : "=r"(a) : "l"(p));
    return a;
}
static __device__ __forceinline__ uint32_t h2u(__half2 h) {
    return *reinterpret_cast<uint32_t*>(&h);
}
static __device__ __forceinline__ void cp16(uint32_t dst, const void* src) {
    asm volatile("cp.async.cg.shared.global [%0], [%1], 16;"
                 :: "r"(dst), "l"(src) : "memory");
}
#define CP_COMMIT() asm volatile("cp.async.commit_group;" ::: "memory")
#define CP_WAIT1()  asm volatile("cp.async.wait_group 1;" ::: "memory")

static __device__ __forceinline__ void ldsm_x4(uint32_t* r, uint32_t addr) {
    asm volatile("ldmatrix.sync.aligned.m8n8.x4.shared.b16 {%0,%1,%2,%3}, [%4];"
                 : "=r"(r[0]), "=r"(r[1]), "=r"(r[2]), "=r"(r[3]) : "r"(addr));
}
static __device__ __forceinline__ void ldsm_x4_t(uint32_t* r, uint32_t addr) {
    asm volatile("ldmatrix.sync.aligned.m8n8.x4.trans.shared.b16 {%0,%1,%2,%3}, [%4];"
                 : "=r"(r[0]), "=r"(r[1]), "=r"(r[2]), "=r"(r[3]) : "r"(addr));
}
static __device__ __forceinline__ void mma16816(float* c, const uint32_t* a,
                                                const uint32_t* b) {
    asm volatile(
        "mma.sync.aligned.m16n8k16.row.col.f32.f16.f16.f32 "
        "{%0,%1,%2,%3}, {%4,%5,%6,%7}, {%8,%9}, {%0,%1,%2,%3};"
        : "+f"(c[0]), "+f"(c[1]), "+f"(c[2]), "+f"(c[3])
        : "r"(a[0]), "r"(a[1]), "r"(a[2]), "r"(a[3]), "r"(b[0]), "r"(b[1]));
}

/* ------------------------------------------------------------------ */
/* single-CTA routing: detect dtype, histogram, padded scan, scatter   */
/* ------------------------------------------------------------------ */
__global__ void k_route(const int* __restrict__ ei) {
    __shared__ int s_cnt[N_EXPERTS];
    __shared__ int s_off[N_EXPERTS + 1];
    __shared__ int s_fill[N_EXPERTS];
    const int tid = threadIdx.x;               /* 1024 threads */
    if (tid < N_EXPERTS) { s_cnt[tid] = 0; s_fill[tid] = 0; }
    for (int i = tid; i < MAX_PAD; i += 1024) g_idx[i] = 0;
    __syncthreads();

    /* int32 vs int64 expert_indices (jax x64): if int64 LE, all high words 0 */
    int bad = 0;
    for (int i = tid; i < NSLOT / 2; i += 1024)
        bad |= (ei[2 * i + 1] != 0);
    const int is64 = !__syncthreads_or(bad);

    /* warp-aggregated histogram */
    for (int i = tid; i < NSLOT; i += 1024) {
        const int e = is64 ? ei[2 * i] : ei[i];
        const unsigned m = __match_any_sync(0xffffffffu, e);
        if ((tid & 31) == __ffs(m) - 1)
            atomicAdd(&s_cnt[e], __popc(m));
    }
    __syncthreads();
    if (tid == 0) {
        int off = 0;
        for (int e = 0; e < N_EXPERTS; e++) {
            s_off[e] = off; g_padOff[e] = off;
            off += (s_cnt[e] + 127) & ~127;
        }
        s_off[N_EXPERTS] = off; g_padOff[N_EXPERTS] = off;
    }
    __syncthreads();

    /* warp-aggregated scatter */
    for (int i = tid; i < NSLOT; i += 1024) {
        const int e = is64 ? ei[2 * i] : ei[i];
        const unsigned m = __match_any_sync(0xffffffffu, e);
        const int leader = __ffs(m) - 1;
        const int rank = __popc(m & ((1u << (tid & 31)) - 1));
        int base = 0;
        if ((tid & 31) == leader) base = atomicAdd(&s_fill[e], __popc(m));
        base = __shfl_sync(0xffffffffu, base, leader);
        const int pos = s_off[e] + base + rank;
        g_idx[pos] = i >> 1;
        g_slotpos[i] = pos;
    }
}

/* fp32 -> fp16 convert for all three weight tensors in one launch */
#define W4 (N_EXPERTS * HIDDEN * INTER / 4)
__global__ void k_cvt3(const float4* __restrict__ g, const float4* __restrict__ u,
                       const float4* __restrict__ d, uint2* __restrict__ wg,
                       uint2* __restrict__ wu, uint2* __restrict__ wd) {
    int i = blockIdx.x * blockDim.x + threadIdx.x;
    if (i >= 3 * W4) return;
    const float4* src; uint2* dst; int j;
    if (i < W4)            { src = g; dst = wg; j = i; }
    else if (i < 2 * W4)   { src = u; dst = wu; j = i - W4; }
    else                   { src = d; dst = wd; j = i - 2 * W4; }
    float4 v = src[j];
    dst[j] = make_uint2(h2u(__floats2half2_rn(v.x, v.y)),
                        h2u(__floats2half2_rn(v.z, v.w)));
}

/* gather token rows into padded fp16 slot matrix g_A */
__global__ void k_gather(const float* __restrict__ tokens) {
    int i = blockIdx.x * blockDim.x + threadIdx.x;
    if (i >= MAX_PAD * (HIDDEN / 4)) return;
    const int slot = i / (HIDDEN / 4);
    const int h4 = (i % (HIDDEN / 4)) * 4;
    const float4 v = *(const float4*)(tokens + (size_t)g_idx[slot] * HIDDEN + h4);
    *(uint2*)(g_A + (size_t)slot * HIDDEN + h4) =
        make_uint2(h2u(__floats2half2_rn(v.x, v.y)),
                   h2u(__floats2half2_rn(v.z, v.w)));
}

/* ------------------------------------------------------------------ */
/* GEMM1: g_H = silu(X@Wg) * (X@Wu); tile 128m x 64n (G+U)             */
/* grid (MTILES, INTER/64), 256 thr, 3-stage cp.async, KC=64           */
/* race-free order: wait(1) -> sync -> prefetch(c+2) -> compute(c)     */
/* ------------------------------------------------------------------ */
__global__ void __launch_bounds__(256, 2)
k_gemm1() {
    extern __shared__ __half dsm[];

    const int mstart = blockIdx.x * 128;
    if (mstart >= g_padOff[N_EXPERTS]) return;
    const int nb = blockIdx.y * 64;

    int e = 0;
#pragma unroll
    for (int q = 1; q < N_EXPERTS; q++)
        if (g_padOff[q] <= mstart) e = q;

    const int tid = threadIdx.x;
    const int lane = tid & 31, wid = tid >> 5;
    const int wm = wid >> 2, wn = wid & 3;

    const __half* gp = g_Wg + (size_t)e * HIDDEN * INTER + nb;
    const __half* up = g_Wu + (size_t)e * HIDDEN * INTER + nb;
    const __half* ap = g_A + (size_t)mstart * HIDDEN;

    const uint32_t smBase = smem_u32(dsm);
    uint32_t stA[3], stG[3], stU[3];
#pragma unroll
    for (int s = 0; s < 3; s++) {
        stA[s] = smBase + (s * G1_ST + G1_A) * 2;
        stG[s] = smBase + (s * G1_ST + G1_BG) * 2;
        stU[s] = smBase + (s * G1_ST + G1_BU) * 2;
    }

    const int ar = tid >> 3, as = tid & 7;   /* A: rows ar+32i, seg as */

    float cG[4][2][4] = {}, cU[4][2][4] = {};
    const int C = HIDDEN / KC;                  /* 16 */

#define G1_LOAD(s, c) do {                                                    \
        const int k0 = (c) * KC;                                              \
        _Pragma("unroll")                                                     \
        for (int i = 0; i < 4; i++)                                           \
            cp16(stA[s] + ((ar + 32 * i) * LDA + as * 8) * 2,                 \
                 ap + (size_t)(ar + 32 * i) * HIDDEN + k0 + as * 8);          \
        _Pragma("unroll")                                                     \
        for (int i = 0; i < 2; i++) {                                         \
            cp16(stG[s] + ((ar + 32 * i) * LDB + as * 8) * 2,                 \
                 gp + (size_t)(k0 + ar + 32 * i) * INTER + as * 8);           \
            cp16(stU[s] + ((ar + 32 * i) * LDB + as * 8) * 2,                 \
                 up + (size_t)(k0 + ar + 32 * i) * INTER + as * 8);           \
        }                                                                     \
    } while (0)

    G1_LOAD(0, 0); CP_COMMIT();
    G1_LOAD(1, 1); CP_COMMIT();

    int st = 0, nst = 2;
    for (int c = 0; c < C; c++) {
        CP_WAIT1();                 /* chunk c resident (≤1 pending group) */
        __syncthreads();            /* all warps done with stage nst       */
        if (c + 2 < C) G1_LOAD(nst, c + 2);
        CP_COMMIT();                /* unconditional: keeps group count aligned */

#pragma unroll
        for (int ks = 0; ks < 4; ks++) {
            const int k0 = ks * 16;
            uint32_t a[4][4];
#pragma unroll
            for (int mt = 0; mt < 4; mt++)
                ldsm_x4(a[mt], stA[st] +
                    ((wm * 64 + mt * 16 + (lane & 15)) * LDA + k0 + ((lane >> 4) << 3)) * 2);
            uint32_t bg[4], bu[4];
            const uint32_t boff =
                ((k0 + (lane & 15)) * LDB + wn * 16 + ((lane >> 4) << 3)) * 2;
            ldsm_x4_t(bg, stG[st] + boff);
            ldsm_x4_t(bu, stU[st] + boff);
#pragma unroll
            for (int mt = 0; mt < 4; mt++) {
#pragma unroll
                for (int nt = 0; nt < 2; nt++) {
                    mma16816(cG[mt][nt], a[mt], bg + 2 * nt);
                    mma16816(cU[mt][nt], a[mt], bu + 2 * nt);
                }
            }
        }
        st = (st == 2) ? 0 : st + 1;
        nst = (nst == 2) ? 0 : nst + 1;
    }

    /* epilogue: silu(G) * U -> fp16 g_H */
    const int rbase = mstart + wm * 64 + (lane >> 2);
    const int cbase = nb + wn * 16 + (lane & 3) * 2;
#pragma unroll
    for (int mt = 0; mt < 4; mt++) {
#pragma unroll
        for (int nt = 0; nt < 2; nt++) {
#pragma unroll
            for (int hh = 0; hh < 2; hh++) {
                float g0 = cG[mt][nt][hh * 2], g1 = cG[mt][nt][hh * 2 + 1];
                float u0 = cU[mt][nt][hh * 2], u1 = cU[mt][nt][hh * 2 + 1];
                float h0 = g0 * u0 / (1.0f + __expf(-g0));
                float h1 = g1 * u1 / (1.0f + __expf(-g1));
                const int slot = rbase + mt * 16 + hh * 8;
                *(__half2*)&g_H[(size_t)slot * INTER + cbase + nt * 8] =
                    __floats2half2_rn(h0, h1);
            }
        }
    }
}

/* ------------------------------------------------------------------ */
/* GEMM2: g_O = H @ Wd; tile 128m x 128n                               */
/* grid (MTILES, HIDDEN/128), 256 thr, 3-stage cp.async, KC=64         */
/* ------------------------------------------------------------------ */
__global__ void __launch_bounds__(256, 2)
k_gemm2() {
    extern __shared__ __half dsm[];

    const int mstart = blockIdx.x * 128;
    if (mstart >= g_padOff[N_EXPERTS]) return;
    const int nb = blockIdx.y * 128;

    int e = 0;
#pragma unroll
    for (int q = 1; q < N_EXPERTS; q++)
        if (g_padOff[q] <= mstart) e = q;

    const int tid = threadIdx.x;
    const int lane = tid & 31, wid = tid >> 5;
    const int wm = wid >> 2, wn = wid & 3;    /* warp tile 64m x 32n */

    const __half* dp = g_Wd + (size_t)e * INTER * HIDDEN + nb;
    const __half* ap = g_H + (size_t)mstart * INTER;

    const uint32_t smBase = smem_u32(dsm);
    uint32_t stA[3], stB[3];
#pragma unroll
    for (int s = 0; s < 3; s++) {
        stA[s] = smBase + (s * G2_ST + G2_A) * 2;
        stB[s] = smBase + (s * G2_ST + G2_B) * 2;
    }

    const int ar = tid >> 3, as = tid & 7;   /* A rows        */
    const int br = tid >> 4, bs = tid & 15;  /* B rows (128w) */

    float cD[4][4][4] = {};
    const int C = INTER / KC;                   /* 32 */

#define G2_LOAD(s, c) do {                                                    \
        const int k0 = (c) * KC;                                              \
        _Pragma("unroll")                                                     \
        for (int i = 0; i < 4; i++)                                           \
            cp16(stA[s] + ((ar + 32 * i) * LDA + as * 8) * 2,                 \
                 ap + (size_t)(ar + 32 * i) * INTER + k0 + as * 8);           \
        _Pragma("unroll")                                                     \
        for (int i = 0; i < 4; i++)                                           \
            cp16(stB[s] + ((br + 16 * i) * LDB2 + bs * 8) * 2,                \
                 dp + (size_t)(k0 + br + 16 * i) * HIDDEN + bs * 8);          \
    } while (0)

    G2_LOAD(0, 0); CP_COMMIT();
    G2_LOAD(1, 1); CP_COMMIT();

    int st = 0, nst = 2;
    for (int c = 0; c < C; c++) {
        CP_WAIT1();
        __syncthreads();
        if (c + 2 < C) G2_LOAD(nst, c + 2);
        CP_COMMIT();

#pragma unroll
        for (int ks = 0; ks < 4; ks++) {
            const int k0 = ks * 16;
            uint32_t a[4][4];
#pragma unroll
            for (int mt = 0; mt < 4; mt++)
                ldsm_x4(a[mt], stA[st] +
                    ((wm * 64 + mt * 16 + (lane & 15)) * LDA + k0 + ((lane >> 4) << 3)) * 2);
            uint32_t bb[2][4];
#pragma unroll
            for (int nn = 0; nn < 2; nn++)
                ldsm_x4_t(bb[nn], stB[st] +
                    ((k0 + (lane & 15)) * LDB2 + wn * 32 + nn * 16 + ((lane >> 4) << 3)) * 2);
#pragma unroll
            for (int mt = 0; mt < 4; mt++) {
#pragma unroll
                for (int nt = 0; nt < 4; nt++)
                    mma16816(cD[mt][nt], a[mt], bb[nt >> 1] + 2 * (nt & 1));
            }
        }
        st = (st == 2) ? 0 : st + 1;
        nst = (nst == 2) ? 0 : nst + 1;
    }

    /* epilogue: plain fp32 stores to per-slot buffer (no atomics) */
    const int rbase = mstart + wm * 64 + (lane >> 2);
    const int cbase = nb + wn * 32 + (lane & 3) * 2;
#pragma unroll
    for (int mt = 0; mt < 4; mt++) {
#pragma unroll
        for (int nt = 0; nt < 4; nt++) {
#pragma unroll
            for (int hh = 0; hh < 2; hh++) {
                const int slot = rbase + mt * 16 + hh * 8;
                *(float2*)&g_O[(size_t)slot * HIDDEN + cbase + nt * 8] =
                    make_float2(cD[mt][nt][hh * 2], cD[mt][nt][hh * 2 + 1]);
            }
        }
    }
}

/* ------------------------------------------------------------------ */
/* combine: out[n] = ew[n,0]*g_O[pos(n,0)] + ew[n,1]*g_O[pos(n,1)]     */
/* ------------------------------------------------------------------ */
__global__ void k_combine(const float* __restrict__ ew, float* __restrict__ out) {
    int i = blockIdx.x * blockDim.x + threadIdx.x;
    if (i >= N_TOKENS * HIDDEN / 4) return;
    const int n = i / (HIDDEN / 4);
    const int h4 = (i % (HIDDEN / 4)) * 4;
    const int p0 = g_slotpos[2 * n], p1 = g_slotpos[2 * n + 1];
    const float w0 = ew[2 * n], w1 = ew[2 * n + 1];
    const float4 a = *(const float4*)&g_O[(size_t)p0 * HIDDEN + h4];
    const float4 b = *(const float4*)&g_O[(size_t)p1 * HIDDEN + h4];
    float4 o;
    o.x = w0 * a.x + w1 * b.x;
    o.y = w0 * a.y + w1 * b.y;
    o.z = w0 * a.z + w1 * b.z;
    o.w = w0 * a.w + w1 * b.w;
    ((float4*)out)[i] = o;
}

/* ------------------------------------------------------------------ */
extern "C" void kernel_launch(void* const* d_in, const int* in_sizes, int n_in,
                              void* d_out, int out_size) {
    const float* tokens = (const float*)d_in[0];
    const int*   ei     = (const int*)d_in[1];
    const float* ew     = (const float*)d_in[2];
    const float* gw     = (const float*)d_in[3];
    const float* uw     = (const float*)d_in[4];
    const float* dw     = (const float*)d_in[5];
    float* out = (float*)d_out;
    (void)in_sizes; (void)n_in; (void)out_size;

    __half *wg, *wu, *wd;
    cudaGetSymbolAddress((void**)&wg, g_Wg);
    cudaGetSymbolAddress((void**)&wu, g_Wu);
    cudaGetSymbolAddress((void**)&wd, g_Wd);
    cudaFuncSetAttribute(k_gemm1, cudaFuncAttributeMaxDynamicSharedMemorySize, G1_SMEM);
    cudaFuncSetAttribute(k_gemm2, cudaFuncAttributeMaxDynamicSharedMemorySize, G2_SMEM);

    k_route<<<1, 1024>>>(ei);
    k_cvt3<<<(3 * W4 + 255) / 256, 256>>>((const float4*)gw, (const float4*)uw,
                                          (const float4*)dw, (uint2*)wg,
                                          (uint2*)wu, (uint2*)wd);
    k_gather<<<(MAX_PAD * (HIDDEN / 4) + 255) / 256, 256>>>(tokens);

    k_gemm1<<<dim3(MTILES, INTER / 64), 256, G1_SMEM>>>();
    k_gemm2<<<dim3(MTILES, HIDDEN / 128), 256, G2_SMEM>>>();
    k_combine<<<(N_TOKENS * HIDDEN / 4 + 255) / 256, 256>>>(ew, out);
}

// round 9
// speedup vs baseline: 1.6000x; 1.0060x over previous
#include <cuda_runtime.h>
#include <cuda_fp16.h>
#include <cstdint>

#define N_TOKENS 4096
#define TOP_K    2
#define N_EXPERTS 8
#define HIDDEN   1024
#define INTER    2048
#define NSLOT    (N_TOKENS*TOP_K)            /* 8192 */
#define MAX_PAD  (NSLOT + N_EXPERTS*128)     /* 9216 */
#define MTILES   (MAX_PAD/128)               /* 72 */

#define KC    64       /* K-chunk per pipeline stage             */
#define LDA   72       /* A smem row stride (halves): 64 + 8 pad */
#define LDB   72       /* B smem row stride (halves, 64-wide)    */
#define LDB2  136      /* B smem row stride (halves, 128-wide)   */

/* gemm1 stage layout (halves): A | Bg | Bu */
#define G1_A    0
#define G1_BG   (128*LDA)                     /* 9216  */
#define G1_BU   (G1_BG + KC*LDB)              /* 13824 */
#define G1_ST   (G1_BU + KC*LDB)              /* 18432 halves = 36864 B */
#define G1_SMEM (3*G1_ST*2)                   /* 110592 B */

/* gemm2 stage layout (halves): A | B */
#define G2_A    0
#define G2_B    (128*LDA)                     /* 9216 */
#define G2_ST   (G2_B + KC*LDB2)              /* 17920 halves = 35840 B */
#define G2_SMEM (3*G2_ST*2)                   /* 107520 B */

/* ------------------------------------------------------------------ */
/* device scratch (static: no allocation allowed)                      */
/* ------------------------------------------------------------------ */
__device__ int    g_idx[MAX_PAD];
__device__ int    g_slotpos[NSLOT];
__device__ int    g_padOff[N_EXPERTS + 1];
__device__ __half g_A[(size_t)MAX_PAD * HIDDEN];            /* gathered fp16 tokens */
__device__ __half g_H[(size_t)MAX_PAD * INTER];             /* fp16 hidden          */
__device__ __half g_O[(size_t)MAX_PAD * HIDDEN];            /* fp16 per-slot out    */
__device__ __half g_Wg[(size_t)N_EXPERTS * HIDDEN * INTER];
__device__ __half g_Wu[(size_t)N_EXPERTS * HIDDEN * INTER];
__device__ __half g_Wd[(size_t)N_EXPERTS * INTER * HIDDEN];

/* ------------------------------------------------------------------ */
/* helpers                                                             */
/* ------------------------------------------------------------------ */
static __device__ __forceinline__ uint32_t smem_u32(const void* p) {
    uint32_t a;
    asm("{ .reg .u64 t; cvta.to.shared.u64 t, %1; cvt.u32.u64 %0, t; }"
        : "=r"(a) : "l"(p));
    return a;
}
static __device__ __forceinline__ uint32_t h2u(__half2 h) {
    return *reinterpret_cast<uint32_t*>(&h);
}
static __device__ __forceinline__ void cp16(uint32_t dst, const void* src) {
    asm volatile("cp.async.cg.shared.global [%0], [%1], 16;"
                 :: "r"(dst), "l"(src) : "memory");
}
#define MB_INIT(addr, cnt)                                                    \
    asm volatile("mbarrier.init.shared.b64 [%0], %1;"                         \
                 :: "r"(addr), "r"((uint32_t)(cnt)) : "memory")
#define MB_ARRIVE(addr)                                                       \
    asm volatile("mbarrier.arrive.shared.b64 _, [%0];" :: "r"(addr) : "memory")
/* .noinc: arrival consumes the baseline init count (init already accounts
   for one arrival per thread per phase). Without .noinc the op is
   self-balancing (+1 pending / -1 on completion) and the barrier NEVER
   flips -> hang (R8 post-mortem). */
#define CP_MBAR(addr)                                                         \
    asm volatile("cp.async.mbarrier.arrive.noinc.shared.b64 [%0];"            \
                 :: "r"(addr) : "memory")
#define MB_WAIT(mbar, ph) do {                                                \
    asm volatile("{\n\t.reg .pred P1;\n\tWAIT_%=:\n\t"                        \
        "mbarrier.try_wait.parity.acquire.cta.shared::cta.b64 P1, [%0], %1, 0x989680;\n\t" \
        "@P1 bra.uni DONE_%=;\n\tbra.uni WAIT_%=;\n\tDONE_%=:\n\t}"           \
        :: "r"(mbar), "r"((uint32_t)(ph)) : "memory");                        \
} while (0)

static __device__ __forceinline__ void ldsm_x4(uint32_t* r, uint32_t addr) {
    asm volatile("ldmatrix.sync.aligned.m8n8.x4.shared.b16 {%0,%1,%2,%3}, [%4];"
                 : "=r"(r[0]), "=r"(r[1]), "=r"(r[2]), "=r"(r[3]) : "r"(addr));
}
static __device__ __forceinline__ void ldsm_x4_t(uint32_t* r, uint32_t addr) {
    asm volatile("ldmatrix.sync.aligned.m8n8.x4.trans.shared.b16 {%0,%1,%2,%3}, [%4];"
                 : "=r"(r[0]), "=r"(r[1]), "=r"(r[2]), "=r"(r[3]) : "r"(addr));
}
static __device__ __forceinline__ void mma16816(float* c, const uint32_t* a,
                                                const uint32_t* b) {
    asm volatile(
        "mma.sync.aligned.m16n8k16.row.col.f32.f16.f16.f32 "
        "{%0,%1,%2,%3}, {%4,%5,%6,%7}, {%8,%9}, {%0,%1,%2,%3};"
        : "+f"(c[0]), "+f"(c[1]), "+f"(c[2]), "+f"(c[3])
        : "r"(a[0]), "r"(a[1]), "r"(a[2]), "r"(a[3]), "r"(b[0]), "r"(b[1]));
}

/* ------------------------------------------------------------------ */
/* single-CTA routing: detect dtype, histogram, padded scan, scatter   */
/* ------------------------------------------------------------------ */
__global__ void k_route(const int* __restrict__ ei) {
    __shared__ int s_cnt[N_EXPERTS];
    __shared__ int s_off[N_EXPERTS + 1];
    __shared__ int s_fill[N_EXPERTS];
    const int tid = threadIdx.x;               /* 1024 threads */
    if (tid < N_EXPERTS) { s_cnt[tid] = 0; s_fill[tid] = 0; }
    for (int i = tid; i < MAX_PAD; i += 1024) g_idx[i] = 0;
    __syncthreads();

    /* int32 vs int64 expert_indices (jax x64): if int64 LE, all high words 0 */
    int bad = 0;
    for (int i = tid; i < NSLOT / 2; i += 1024)
        bad |= (ei[2 * i + 1] != 0);
    const int is64 = !__syncthreads_or(bad);

    for (int i = tid; i < NSLOT; i += 1024) {
        const int e = is64 ? ei[2 * i] : ei[i];
        const unsigned m = __match_any_sync(0xffffffffu, e);
        if ((tid & 31) == __ffs(m) - 1)
            atomicAdd(&s_cnt[e], __popc(m));
    }
    __syncthreads();
    if (tid == 0) {
        int off = 0;
        for (int e = 0; e < N_EXPERTS; e++) {
            s_off[e] = off; g_padOff[e] = off;
            off += (s_cnt[e] + 127) & ~127;
        }
        s_off[N_EXPERTS] = off; g_padOff[N_EXPERTS] = off;
    }
    __syncthreads();

    for (int i = tid; i < NSLOT; i += 1024) {
        const int e = is64 ? ei[2 * i] : ei[i];
        const unsigned m = __match_any_sync(0xffffffffu, e);
        const int leader = __ffs(m) - 1;
        const int rank = __popc(m & ((1u << (tid & 31)) - 1));
        int base = 0;
        if ((tid & 31) == leader) base = atomicAdd(&s_fill[e], __popc(m));
        base = __shfl_sync(0xffffffffu, base, leader);
        const int pos = s_off[e] + base + rank;
        g_idx[pos] = i >> 1;
        g_slotpos[i] = pos;
    }
}

/* fp32 -> fp16 convert for all three weight tensors in one launch */
#define W4 (N_EXPERTS * HIDDEN * INTER / 4)
__global__ void k_cvt3(const float4* __restrict__ g, const float4* __restrict__ u,
                       const float4* __restrict__ d, uint2* __restrict__ wg,
                       uint2* __restrict__ wu, uint2* __restrict__ wd) {
    int i = blockIdx.x * blockDim.x + threadIdx.x;
    if (i >= 3 * W4) return;
    const float4* src; uint2* dst; int j;
    if (i < W4)            { src = g; dst = wg; j = i; }
    else if (i < 2 * W4)   { src = u; dst = wu; j = i - W4; }
    else                   { src = d; dst = wd; j = i - 2 * W4; }
    float4 v = src[j];
    dst[j] = make_uint2(h2u(__floats2half2_rn(v.x, v.y)),
                        h2u(__floats2half2_rn(v.z, v.w)));
}

/* gather token rows into padded fp16 slot matrix g_A */
__global__ void k_gather(const float* __restrict__ tokens) {
    int i = blockIdx.x * blockDim.x + threadIdx.x;
    if (i >= MAX_PAD * (HIDDEN / 4)) return;
    const int slot = i / (HIDDEN / 4);
    const int h4 = (i % (HIDDEN / 4)) * 4;
    const float4 v = *(const float4*)(tokens + (size_t)g_idx[slot] * HIDDEN + h4);
    *(uint2*)(g_A + (size_t)slot * HIDDEN + h4) =
        make_uint2(h2u(__floats2half2_rn(v.x, v.y)),
                   h2u(__floats2half2_rn(v.z, v.w)));
}

/* ------------------------------------------------------------------ */
/* GEMM1: g_H = silu(X@Wg) * (X@Wu); tile 128m x 64n (G+U)             */
/* grid (MTILES, INTER/64), 256 thr, 3-stage mbarrier pipeline         */
/* ------------------------------------------------------------------ */
__global__ void __launch_bounds__(256, 2)
k_gemm1() {
    extern __shared__ __half dsm[];

    const int mstart = blockIdx.x * 128;
    if (mstart >= g_padOff[N_EXPERTS]) return;
    const int nb = blockIdx.y * 64;

    int e = 0;
#pragma unroll
    for (int q = 1; q < N_EXPERTS; q++)
        if (g_padOff[q] <= mstart) e = q;

    const int tid = threadIdx.x;
    const int lane = tid & 31, wid = tid >> 5;
    const int wm = wid >> 2, wn = wid & 3;

    const __half* gp = g_Wg + (size_t)e * HIDDEN * INTER + nb;
    const __half* up = g_Wu + (size_t)e * HIDDEN * INTER + nb;
    const __half* ap = g_A + (size_t)mstart * HIDDEN;

    const uint32_t smBase = smem_u32(dsm);
    uint32_t stA[3], stG[3], stU[3];
#pragma unroll
    for (int s = 0; s < 3; s++) {
        stA[s] = smBase + (s * G1_ST + G1_A) * 2;
        stG[s] = smBase + (s * G1_ST + G1_BG) * 2;
        stU[s] = smBase + (s * G1_ST + G1_BU) * 2;
    }
    /* mbarriers: full[3] (count 256, cp.async.noinc-armed), empty[3] (count 8) */
    __shared__ __align__(8) uint64_t s_mb[6];
    const uint32_t mbBase = smem_u32(s_mb);
    if (tid == 0) {
#pragma unroll
        for (int s = 0; s < 3; s++) {
            MB_INIT(mbBase + 8 * s, 256);          /* full  */
            MB_INIT(mbBase + 24 + 8 * s, 8);       /* empty */
        }
    }
    __syncthreads();

    const int ar = tid >> 3, as = tid & 7;

    float cG[4][2][4] = {}, cU[4][2][4] = {};
    const int C = HIDDEN / KC;                  /* 16 */

#define G1_LOAD(s, c) do {                                                    \
        const int k0 = (c) * KC;                                              \
        _Pragma("unroll")                                                     \
        for (int i = 0; i < 4; i++)                                           \
            cp16(stA[s] + ((ar + 32 * i) * LDA + as * 8) * 2,                 \
                 ap + (size_t)(ar + 32 * i) * HIDDEN + k0 + as * 8);          \
        _Pragma("unroll")                                                     \
        for (int i = 0; i < 2; i++) {                                         \
            cp16(stG[s] + ((ar + 32 * i) * LDB + as * 8) * 2,                 \
                 gp + (size_t)(k0 + ar + 32 * i) * INTER + as * 8);           \
            cp16(stU[s] + ((ar + 32 * i) * LDB + as * 8) * 2,                 \
                 up + (size_t)(k0 + ar + 32 * i) * INTER + as * 8);           \
        }                                                                     \
    } while (0)

    G1_LOAD(0, 0); CP_MBAR(mbBase + 0);
    G1_LOAD(1, 1); CP_MBAR(mbBase + 8);

    for (int c = 0; c < C; c++) {
        const int s = c % 3;
        const int n = c + 2;
        if (n < C) {
            const int s2 = n % 3;
            if (n >= 3)  /* stage reuse: wait all warps done chunk n-3 */
                MB_WAIT(mbBase + 24 + 8 * s2, (uint32_t)(((n / 3) - 1) & 1));
            G1_LOAD(s2, n);
            CP_MBAR(mbBase + 8 * s2);
        }
        MB_WAIT(mbBase + 8 * s, (uint32_t)((c / 3) & 1));   /* chunk c data */

#pragma unroll
        for (int ks = 0; ks < 4; ks++) {
            const int k0 = ks * 16;
            uint32_t a[4][4];
#pragma unroll
            for (int mt = 0; mt < 4; mt++)
                ldsm_x4(a[mt], stA[s] +
                    ((wm * 64 + mt * 16 + (lane & 15)) * LDA + k0 + ((lane >> 4) << 3)) * 2);
            uint32_t bg[4], bu[4];
            const uint32_t boff =
                ((k0 + (lane & 15)) * LDB + wn * 16 + ((lane >> 4) << 3)) * 2;
            ldsm_x4_t(bg, stG[s] + boff);
            ldsm_x4_t(bu, stU[s] + boff);
#pragma unroll
            for (int mt = 0; mt < 4; mt++) {
#pragma unroll
                for (int nt = 0; nt < 2; nt++) {
                    mma16816(cG[mt][nt], a[mt], bg + 2 * nt);
                    mma16816(cU[mt][nt], a[mt], bu + 2 * nt);
                }
            }
        }
        if (lane == 0) MB_ARRIVE(mbBase + 24 + 8 * s);      /* stage free */
    }

    /* epilogue: silu(G) * U -> fp16 g_H */
    const int rbase = mstart + wm * 64 + (lane >> 2);
    const int cbase = nb + wn * 16 + (lane & 3) * 2;
#pragma unroll
    for (int mt = 0; mt < 4; mt++) {
#pragma unroll
        for (int nt = 0; nt < 2; nt++) {
#pragma unroll
            for (int hh = 0; hh < 2; hh++) {
                float g0 = cG[mt][nt][hh * 2], g1 = cG[mt][nt][hh * 2 + 1];
                float u0 = cU[mt][nt][hh * 2], u1 = cU[mt][nt][hh * 2 + 1];
                float h0 = g0 * u0 / (1.0f + __expf(-g0));
                float h1 = g1 * u1 / (1.0f + __expf(-g1));
                const int slot = rbase + mt * 16 + hh * 8;
                *(__half2*)&g_H[(size_t)slot * INTER + cbase + nt * 8] =
                    __floats2half2_rn(h0, h1);
            }
        }
    }
}

/* ------------------------------------------------------------------ */
/* GEMM2: g_O = H @ Wd (fp16 out); tile 128m x 128n                    */
/* grid (MTILES, HIDDEN/128), 256 thr, 3-stage mbarrier pipeline       */
/* ------------------------------------------------------------------ */
__global__ void __launch_bounds__(256, 2)
k_gemm2() {
    extern __shared__ __half dsm[];

    const int mstart = blockIdx.x * 128;
    if (mstart >= g_padOff[N_EXPERTS]) return;
    const int nb = blockIdx.y * 128;

    int e = 0;
#pragma unroll
    for (int q = 1; q < N_EXPERTS; q++)
        if (g_padOff[q] <= mstart) e = q;

    const int tid = threadIdx.x;
    const int lane = tid & 31, wid = tid >> 5;
    const int wm = wid >> 2, wn = wid & 3;    /* warp tile 64m x 32n */

    const __half* dp = g_Wd + (size_t)e * INTER * HIDDEN + nb;
    const __half* ap = g_H + (size_t)mstart * INTER;

    const uint32_t smBase = smem_u32(dsm);
    uint32_t stA[3], stB[3];
#pragma unroll
    for (int s = 0; s < 3; s++) {
        stA[s] = smBase + (s * G2_ST + G2_A) * 2;
        stB[s] = smBase + (s * G2_ST + G2_B) * 2;
    }
    __shared__ __align__(8) uint64_t s_mb[6];
    const uint32_t mbBase = smem_u32(s_mb);
    if (tid == 0) {
#pragma unroll
        for (int s = 0; s < 3; s++) {
            MB_INIT(mbBase + 8 * s, 256);
            MB_INIT(mbBase + 24 + 8 * s, 8);
        }
    }
    __syncthreads();

    const int ar = tid >> 3, as = tid & 7;
    const int br = tid >> 4, bs = tid & 15;

    float cD[4][4][4] = {};
    const int C = INTER / KC;                   /* 32 */

#define G2_LOAD(s, c) do {                                                    \
        const int k0 = (c) * KC;                                              \
        _Pragma("unroll")                                                     \
        for (int i = 0; i < 4; i++)                                           \
            cp16(stA[s] + ((ar + 32 * i) * LDA + as * 8) * 2,                 \
                 ap + (size_t)(ar + 32 * i) * INTER + k0 + as * 8);           \
        _Pragma("unroll")                                                     \
        for (int i = 0; i < 4; i++)                                           \
            cp16(stB[s] + ((br + 16 * i) * LDB2 + bs * 8) * 2,                \
                 dp + (size_t)(k0 + br + 16 * i) * HIDDEN + bs * 8);          \
    } while (0)

    G2_LOAD(0, 0); CP_MBAR(mbBase + 0);
    G2_LOAD(1, 1); CP_MBAR(mbBase + 8);

    for (int c = 0; c < C; c++) {
        const int s = c % 3;
        const int n = c + 2;
        if (n < C) {
            const int s2 = n % 3;
            if (n >= 3)
                MB_WAIT(mbBase + 24 + 8 * s2, (uint32_t)(((n / 3) - 1) & 1));
            G2_LOAD(s2, n);
            CP_MBAR(mbBase + 8 * s2);
        }
        MB_WAIT(mbBase + 8 * s, (uint32_t)((c / 3) & 1));

#pragma unroll
        for (int ks = 0; ks < 4; ks++) {
            const int k0 = ks * 16;
            uint32_t a[4][4];
#pragma unroll
            for (int mt = 0; mt < 4; mt++)
                ldsm_x4(a[mt], stA[s] +
                    ((wm * 64 + mt * 16 + (lane & 15)) * LDA + k0 + ((lane >> 4) << 3)) * 2);
            uint32_t bb[2][4];
#pragma unroll
            for (int nn = 0; nn < 2; nn++)
                ldsm_x4_t(bb[nn], stB[s] +
                    ((k0 + (lane & 15)) * LDB2 + wn * 32 + nn * 16 + ((lane >> 4) << 3)) * 2);
#pragma unroll
            for (int mt = 0; mt < 4; mt++) {
#pragma unroll
                for (int nt = 0; nt < 4; nt++)
                    mma16816(cD[mt][nt], a[mt], bb[nt >> 1] + 2 * (nt & 1));
            }
        }
        if (lane == 0) MB_ARRIVE(mbBase + 24 + 8 * s);
    }

    /* epilogue: fp16 stores to per-slot buffer (no atomics) */
    const int rbase = mstart + wm * 64 + (lane >> 2);
    const int cbase = nb + wn * 32 + (lane & 3) * 2;
#pragma unroll
    for (int mt = 0; mt < 4; mt++) {
#pragma unroll
        for (int nt = 0; nt < 4; nt++) {
#pragma unroll
            for (int hh = 0; hh < 2; hh++) {
                const int slot = rbase + mt * 16 + hh * 8;
                *(__half2*)&g_O[(size_t)slot * HIDDEN + cbase + nt * 8] =
                    __floats2half2_rn(cD[mt][nt][hh * 2], cD[mt][nt][hh * 2 + 1]);
            }
        }
    }
}

/* ------------------------------------------------------------------ */
/* combine: out[n] = ew[n,0]*g_O[pos(n,0)] + ew[n,1]*g_O[pos(n,1)]     */
/* 8 elems per thread (fp16 in, fp32 out)                              */
/* ------------------------------------------------------------------ */
__global__ void k_combine(const float* __restrict__ ew, float* __restrict__ out) {
    int i = blockIdx.x * blockDim.x + threadIdx.x;
    if (i >= N_TOKENS * HIDDEN / 8) return;
    const int n = i / (HIDDEN / 8);
    const int h8 = (i % (HIDDEN / 8)) * 8;
    const int p0 = g_slotpos[2 * n], p1 = g_slotpos[2 * n + 1];
    const float w0 = ew[2 * n], w1 = ew[2 * n + 1];
    const uint4 a = *(const uint4*)&g_O[(size_t)p0 * HIDDEN + h8];
    const uint4 b = *(const uint4*)&g_O[(size_t)p1 * HIDDEN + h8];
    const uint32_t au[4] = {a.x, a.y, a.z, a.w};
    const uint32_t bu[4] = {b.x, b.y, b.z, b.w};
    float o[8];
#pragma unroll
    for (int j = 0; j < 4; j++) {
        float2 fa = __half22float2(*(const __half2*)&au[j]);
        float2 fb = __half22float2(*(const __half2*)&bu[j]);
        o[2 * j]     = w0 * fa.x + w1 * fb.x;
        o[2 * j + 1] = w0 * fa.y + w1 * fb.y;
    }
    float4* op = (float4*)(out + (size_t)n * HIDDEN + h8);
    op[0] = make_float4(o[0], o[1], o[2], o[3]);
    op[1] = make_float4(o[4], o[5], o[6], o[7]);
}

/* ------------------------------------------------------------------ */
extern "C" void kernel_launch(void* const* d_in, const int* in_sizes, int n_in,
                              void* d_out, int out_size) {
    const float* tokens = (const float*)d_in[0];
    const int*   ei     = (const int*)d_in[1];
    const float* ew     = (const float*)d_in[2];
    const float* gw     = (const float*)d_in[3];
    const float* uw     = (const float*)d_in[4];
    const float* dw     = (const float*)d_in[5];
    float* out = (float*)d_out;
    (void)in_sizes; (void)n_in; (void)out_size;

    __half *wg, *wu, *wd;
    cudaGetSymbolAddress((void**)&wg, g_Wg);
    cudaGetSymbolAddress((void**)&wu, g_Wu);
    cudaGetSymbolAddress((void**)&wd, g_Wd);
    cudaFuncSetAttribute(k_gemm1, cudaFuncAttributeMaxDynamicSharedMemorySize, G1_SMEM);
    cudaFuncSetAttribute(k_gemm2, cudaFuncAttributeMaxDynamicSharedMemorySize, G2_SMEM);

    k_route<<<1, 1024>>>(ei);
    k_cvt3<<<(3 * W4 + 255) / 256, 256>>>((const float4*)gw, (const float4*)uw,
                                          (const float4*)dw, (uint2*)wg,
                                          (uint2*)wu, (uint2*)wd);
    k_gather<<<(MAX_PAD * (HIDDEN / 4) + 255) / 256, 256>>>(tokens);

    k_gemm1<<<dim3(MTILES, INTER / 64), 256, G1_SMEM>>>();
    k_gemm2<<<dim3(MTILES, HIDDEN / 128), 256, G2_SMEM>>>();
    k_combine<<<(N_TOKENS * HIDDEN / 8 + 255) / 256, 256>>>(ew, out);
}

// round 11
// speedup vs baseline: 1.6451x; 1.0282x over previous
#include <cuda_runtime.h>
#include <cuda_fp16.h>
#include <cstdint>

#define N_TOKENS 4096
#define TOP_K    2
#define N_EXPERTS 8
#define HIDDEN   1024
#define INTER    2048
#define NSLOT    (N_TOKENS*TOP_K)            /* 8192 */
#define MAX_PAD  (NSLOT + N_EXPERTS*128)     /* 9216 */
#define MTILES   (MAX_PAD/128)               /* 72 */

#define KC    64       /* K-chunk per pipeline stage             */
#define LDA   72       /* A smem row stride (halves): 64 + 8 pad */
#define LDB   72       /* B smem row stride (halves, 64-wide)    */
#define LDB2  136      /* B smem row stride (halves, 128-wide)   */

/* gemm1 stage layout (halves): A | Bg | Bu */
#define G1_A    0
#define G1_BG   (128*LDA)                     /* 9216  */
#define G1_BU   (G1_BG + KC*LDB)              /* 13824 */
#define G1_ST   (G1_BU + KC*LDB)              /* 18432 halves = 36864 B */
#define G1_SMEM (3*G1_ST*2)                   /* 110592 B */

/* gemm2 stage layout (halves): A | B */
#define G2_A    0
#define G2_B    (128*LDA)                     /* 9216 */
#define G2_ST   (G2_B + KC*LDB2)              /* 17920 halves = 35840 B */
#define G2_SMEM (3*G2_ST*2)                   /* 107520 B */

/* ------------------------------------------------------------------ */
/* device scratch (static: no allocation allowed)                      */
/* ------------------------------------------------------------------ */
__device__ int    g_idx[MAX_PAD];
__device__ int    g_slotpos[NSLOT];
__device__ int    g_padOff[N_EXPERTS + 1];
__device__ __half g_A[(size_t)MAX_PAD * HIDDEN];            /* gathered fp16 tokens */
__device__ __half g_H[(size_t)MAX_PAD * INTER];             /* fp16 hidden          */
__device__ __half g_O[(size_t)MAX_PAD * HIDDEN];            /* fp16 per-slot out    */
__device__ __half g_Wg[(size_t)N_EXPERTS * HIDDEN * INTER];
__device__ __half g_Wu[(size_t)N_EXPERTS * HIDDEN * INTER];
__device__ __half g_Wd[(size_t)N_EXPERTS * INTER * HIDDEN];

/* ------------------------------------------------------------------ */
/* helpers                                                             */
/* ------------------------------------------------------------------ */
static __device__ __forceinline__ uint32_t smem_u32(const void* p) {
    uint32_t a;
    asm("{ .reg .u64 t; cvta.to.shared.u64 t, %1; cvt.u32.u64 %0, t; }"
        : "=r"(a) : "l"(p));
    return a;
}
static __device__ __forceinline__ uint32_t h2u(__half2 h) {
    return *reinterpret_cast<uint32_t*>(&h);
}
static __device__ __forceinline__ void cp16(uint32_t dst, const void* src) {
    asm volatile("cp.async.cg.shared.global [%0], [%1], 16;"
                 :: "r"(dst), "l"(src) : "memory");
}
#define CP_COMMIT() asm volatile("cp.async.commit_group;" ::: "memory")
#define CP_WAIT1()  asm volatile("cp.async.wait_group 1;" ::: "memory")

static __device__ __forceinline__ void ldsm_x4(uint32_t* r, uint32_t addr) {
    asm volatile("ldmatrix.sync.aligned.m8n8.x4.shared.b16 {%0,%1,%2,%3}, [%4];"
                 : "=r"(r[0]), "=r"(r[1]), "=r"(r[2]), "=r"(r[3]) : "r"(addr));
}
static __device__ __forceinline__ void ldsm_x4_t(uint32_t* r, uint32_t addr) {
    asm volatile("ldmatrix.sync.aligned.m8n8.x4.trans.shared.b16 {%0,%1,%2,%3}, [%4];"
                 : "=r"(r[0]), "=r"(r[1]), "=r"(r[2]), "=r"(r[3]) : "r"(addr));
}
static __device__ __forceinline__ void mma16816(float* c, const uint32_t* a,
                                                const uint32_t* b) {
    asm volatile(
        "mma.sync.aligned.m16n8k16.row.col.f32.f16.f16.f32 "
        "{%0,%1,%2,%3}, {%4,%5,%6,%7}, {%8,%9}, {%0,%1,%2,%3};"
        : "+f"(c[0]), "+f"(c[1]), "+f"(c[2]), "+f"(c[3])
        : "r"(a[0]), "r"(a[1]), "r"(a[2]), "r"(a[3]), "r"(b[0]), "r"(b[1]));
}

/* ------------------------------------------------------------------ */
/* single-CTA routing: detect dtype, histogram, padded scan, scatter   */
/* ------------------------------------------------------------------ */
__global__ void k_route(const int* __restrict__ ei) {
    __shared__ int s_cnt[N_EXPERTS];
    __shared__ int s_off[N_EXPERTS + 1];
    __shared__ int s_fill[N_EXPERTS];
    const int tid = threadIdx.x;               /* 1024 threads */
    if (tid < N_EXPERTS) { s_cnt[tid] = 0; s_fill[tid] = 0; }
    for (int i = tid; i < MAX_PAD; i += 1024) g_idx[i] = 0;
    __syncthreads();

    /* int32 vs int64 expert_indices (jax x64): if int64 LE, all high words 0 */
    int bad = 0;
    for (int i = tid; i < NSLOT / 2; i += 1024)
        bad |= (ei[2 * i + 1] != 0);
    const int is64 = !__syncthreads_or(bad);

    for (int i = tid; i < NSLOT; i += 1024) {
        const int e = is64 ? ei[2 * i] : ei[i];
        const unsigned m = __match_any_sync(0xffffffffu, e);
        if ((tid & 31) == __ffs(m) - 1)
            atomicAdd(&s_cnt[e], __popc(m));
    }
    __syncthreads();
    if (tid == 0) {
        int off = 0;
        for (int e = 0; e < N_EXPERTS; e++) {
            s_off[e] = off; g_padOff[e] = off;
            off += (s_cnt[e] + 127) & ~127;
        }
        s_off[N_EXPERTS] = off; g_padOff[N_EXPERTS] = off;
    }
    __syncthreads();

    for (int i = tid; i < NSLOT; i += 1024) {
        const int e = is64 ? ei[2 * i] : ei[i];
        const unsigned m = __match_any_sync(0xffffffffu, e);
        const int leader = __ffs(m) - 1;
        const int rank = __popc(m & ((1u << (tid & 31)) - 1));
        int base = 0;
        if ((tid & 31) == leader) base = atomicAdd(&s_fill[e], __popc(m));
        base = __shfl_sync(0xffffffffu, base, leader);
        const int pos = s_off[e] + base + rank;
        g_idx[pos] = i >> 1;
        g_slotpos[i] = pos;
    }
}

/* fp32 -> fp16 convert for one weight tensor */
#define W4 (N_EXPERTS * HIDDEN * INTER / 4)
__global__ void k_cvt(const float4* __restrict__ src, uint2* __restrict__ dst,
                      int n4) {
    int i = blockIdx.x * blockDim.x + threadIdx.x;
    if (i >= n4) return;
    float4 v = src[i];
    dst[i] = make_uint2(h2u(__floats2half2_rn(v.x, v.y)),
                        h2u(__floats2half2_rn(v.z, v.w)));
}

/* gather token rows into padded fp16 slot matrix g_A */
__global__ void k_gather(const float* __restrict__ tokens) {
    int i = blockIdx.x * blockDim.x + threadIdx.x;
    if (i >= MAX_PAD * (HIDDEN / 4)) return;
    const int slot = i / (HIDDEN / 4);
    const int h4 = (i % (HIDDEN / 4)) * 4;
    const float4 v = *(const float4*)(tokens + (size_t)g_idx[slot] * HIDDEN + h4);
    *(uint2*)(g_A + (size_t)slot * HIDDEN + h4) =
        make_uint2(h2u(__floats2half2_rn(v.x, v.y)),
                   h2u(__floats2half2_rn(v.z, v.w)));
}

/* ------------------------------------------------------------------ */
/* GEMM1: g_H = silu(X@Wg) * (X@Wu); tile 128m x 64n (G+U)             */
/* grid (MTILES, INTER/64), 256 thr, 3-stage cp.async                  */
/* ------------------------------------------------------------------ */
__global__ void __launch_bounds__(256, 2)
k_gemm1() {
    extern __shared__ __half dsm[];

    const int mstart = blockIdx.x * 128;
    if (mstart >= g_padOff[N_EXPERTS]) return;
    const int nb = blockIdx.y * 64;

    int e = 0;
#pragma unroll
    for (int q = 1; q < N_EXPERTS; q++)
        if (g_padOff[q] <= mstart) e = q;

    const int tid = threadIdx.x;
    const int lane = tid & 31, wid = tid >> 5;
    const int wm = wid >> 2, wn = wid & 3;

    const __half* gp = g_Wg + (size_t)e * HIDDEN * INTER + nb;
    const __half* up = g_Wu + (size_t)e * HIDDEN * INTER + nb;
    const __half* ap = g_A + (size_t)mstart * HIDDEN;

    const uint32_t smBase = smem_u32(dsm);
    uint32_t stA[3], stG[3], stU[3];
#pragma unroll
    for (int s = 0; s < 3; s++) {
        stA[s] = smBase + (s * G1_ST + G1_A) * 2;
        stG[s] = smBase + (s * G1_ST + G1_BG) * 2;
        stU[s] = smBase + (s * G1_ST + G1_BU) * 2;
    }

    const int ar = tid >> 3, as = tid & 7;

    float cG[4][2][4] = {}, cU[4][2][4] = {};
    const int C = HIDDEN / KC;                  /* 16 */

#define G1_LOAD(s, c) do {                                                    \
        const int k0 = (c) * KC;                                              \
        _Pragma("unroll")                                                     \
        for (int i = 0; i < 4; i++)                                           \
            cp16(stA[s] + ((ar + 32 * i) * LDA + as * 8) * 2,                 \
                 ap + (size_t)(ar + 32 * i) * HIDDEN + k0 + as * 8);          \
        _Pragma("unroll")                                                     \
        for (int i = 0; i < 2; i++) {                                         \
            cp16(stG[s] + ((ar + 32 * i) * LDB + as * 8) * 2,                 \
                 gp + (size_t)(k0 + ar + 32 * i) * INTER + as * 8);           \
            cp16(stU[s] + ((ar + 32 * i) * LDB + as * 8) * 2,                 \
                 up + (size_t)(k0 + ar + 32 * i) * INTER + as * 8);           \
        }                                                                     \
    } while (0)

    G1_LOAD(0, 0); CP_COMMIT();
    G1_LOAD(1, 1); CP_COMMIT();

    int st = 0, nst = 2;
    for (int c = 0; c < C; c++) {
        CP_WAIT1();                 /* own chunk-c copies complete          */
        __syncthreads();            /* collective: chunk c resident,        */
                                    /* all warps done with stage nst        */
        if (c + 2 < C) G1_LOAD(nst, c + 2);
        CP_COMMIT();                /* unconditional: group count aligned   */

#pragma unroll
        for (int ks = 0; ks < 4; ks++) {
            const int k0 = ks * 16;
            uint32_t a[4][4];
#pragma unroll
            for (int mt = 0; mt < 4; mt++)
                ldsm_x4(a[mt], stA[st] +
                    ((wm * 64 + mt * 16 + (lane & 15)) * LDA + k0 + ((lane >> 4) << 3)) * 2);
            uint32_t bg[4], bu[4];
            const uint32_t boff =
                ((k0 + (lane & 15)) * LDB + wn * 16 + ((lane >> 4) << 3)) * 2;
            ldsm_x4_t(bg, stG[st] + boff);
            ldsm_x4_t(bu, stU[st] + boff);
#pragma unroll
            for (int mt = 0; mt < 4; mt++) {
#pragma unroll
                for (int nt = 0; nt < 2; nt++) {
                    mma16816(cG[mt][nt], a[mt], bg + 2 * nt);
                    mma16816(cU[mt][nt], a[mt], bu + 2 * nt);
                }
            }
        }
        st = (st == 2) ? 0 : st + 1;
        nst = (nst == 2) ? 0 : nst + 1;
    }

    /* epilogue: silu(G) * U -> fp16 g_H */
    const int rbase = mstart + wm * 64 + (lane >> 2);
    const int cbase = nb + wn * 16 + (lane & 3) * 2;
#pragma unroll
    for (int mt = 0; mt < 4; mt++) {
#pragma unroll
        for (int nt = 0; nt < 2; nt++) {
#pragma unroll
            for (int hh = 0; hh < 2; hh++) {
                float g0 = cG[mt][nt][hh * 2], g1 = cG[mt][nt][hh * 2 + 1];
                float u0 = cU[mt][nt][hh * 2], u1 = cU[mt][nt][hh * 2 + 1];
                float h0 = g0 * u0 / (1.0f + __expf(-g0));
                float h1 = g1 * u1 / (1.0f + __expf(-g1));
                const int slot = rbase + mt * 16 + hh * 8;
                *(__half2*)&g_H[(size_t)slot * INTER + cbase + nt * 8] =
                    __floats2half2_rn(h0, h1);
            }
        }
    }
}

/* ------------------------------------------------------------------ */
/* GEMM2: g_O = H @ Wd (fp16 out); tile 128m x 128n                    */
/* grid (MTILES, HIDDEN/128), 256 thr, 3-stage cp.async                */
/* ------------------------------------------------------------------ */
__global__ void __launch_bounds__(256, 2)
k_gemm2() {
    extern __shared__ __half dsm[];

    const int mstart = blockIdx.x * 128;
    if (mstart >= g_padOff[N_EXPERTS]) return;
    const int nb = blockIdx.y * 128;

    int e = 0;
#pragma unroll
    for (int q = 1; q < N_EXPERTS; q++)
        if (g_padOff[q] <= mstart) e = q;

    const int tid = threadIdx.x;
    const int lane = tid & 31, wid = tid >> 5;
    const int wm = wid >> 2, wn = wid & 3;    /* warp tile 64m x 32n */

    const __half* dp = g_Wd + (size_t)e * INTER * HIDDEN + nb;
    const __half* ap = g_H + (size_t)mstart * INTER;

    const uint32_t smBase = smem_u32(dsm);
    uint32_t stA[3], stB[3];
#pragma unroll
    for (int s = 0; s < 3; s++) {
        stA[s] = smBase + (s * G2_ST + G2_A) * 2;
        stB[s] = smBase + (s * G2_ST + G2_B) * 2;
    }

    const int ar = tid >> 3, as = tid & 7;
    const int br = tid >> 4, bs = tid & 15;

    float cD[4][4][4] = {};
    const int C = INTER / KC;                   /* 32 */

#define G2_LOAD(s, c) do {                                                    \
        const int k0 = (c) * KC;                                              \
        _Pragma("unroll")                                                     \
        for (int i = 0; i < 4; i++)                                           \
            cp16(stA[s] + ((ar + 32 * i) * LDA + as * 8) * 2,                 \
                 ap + (size_t)(ar + 32 * i) * INTER + k0 + as * 8);           \
        _Pragma("unroll")                                                     \
        for (int i = 0; i < 4; i++)                                           \
            cp16(stB[s] + ((br + 16 * i) * LDB2 + bs * 8) * 2,                \
                 dp + (size_t)(k0 + br + 16 * i) * HIDDEN + bs * 8);          \
    } while (0)

    G2_LOAD(0, 0); CP_COMMIT();
    G2_LOAD(1, 1); CP_COMMIT();

    int st = 0, nst = 2;
    for (int c = 0; c < C; c++) {
        CP_WAIT1();
        __syncthreads();
        if (c + 2 < C) G2_LOAD(nst, c + 2);
        CP_COMMIT();

#pragma unroll
        for (int ks = 0; ks < 4; ks++) {
            const int k0 = ks * 16;
            uint32_t a[4][4];
#pragma unroll
            for (int mt = 0; mt < 4; mt++)
                ldsm_x4(a[mt], stA[st] +
                    ((wm * 64 + mt * 16 + (lane & 15)) * LDA + k0 + ((lane >> 4) << 3)) * 2);
            uint32_t bb[2][4];
#pragma unroll
            for (int nn = 0; nn < 2; nn++)
                ldsm_x4_t(bb[nn], stB[st] +
                    ((k0 + (lane & 15)) * LDB2 + wn * 32 + nn * 16 + ((lane >> 4) << 3)) * 2);
#pragma unroll
            for (int mt = 0; mt < 4; mt++) {
#pragma unroll
                for (int nt = 0; nt < 4; nt++)
                    mma16816(cD[mt][nt], a[mt], bb[nt >> 1] + 2 * (nt & 1));
            }
        }
        st = (st == 2) ? 0 : st + 1;
        nst = (nst == 2) ? 0 : nst + 1;
    }

    /* epilogue: fp16 stores to per-slot buffer (no atomics) */
    const int rbase = mstart + wm * 64 + (lane >> 2);
    const int cbase = nb + wn * 32 + (lane & 3) * 2;
#pragma unroll
    for (int mt = 0; mt < 4; mt++) {
#pragma unroll
        for (int nt = 0; nt < 4; nt++) {
#pragma unroll
            for (int hh = 0; hh < 2; hh++) {
                const int slot = rbase + mt * 16 + hh * 8;
                *(__half2*)&g_O[(size_t)slot * HIDDEN + cbase + nt * 8] =
                    __floats2half2_rn(cD[mt][nt][hh * 2], cD[mt][nt][hh * 2 + 1]);
            }
        }
    }
}

/* ------------------------------------------------------------------ */
/* combine: out[n] = ew[n,0]*g_O[pos(n,0)] + ew[n,1]*g_O[pos(n,1)]     */
/* ------------------------------------------------------------------ */
__global__ void k_combine(const float* __restrict__ ew, float* __restrict__ out) {
    int i = blockIdx.x * blockDim.x + threadIdx.x;
    if (i >= N_TOKENS * HIDDEN / 8) return;
    const int n = i / (HIDDEN / 8);
    const int h8 = (i % (HIDDEN / 8)) * 8;
    const int p0 = g_slotpos[2 * n], p1 = g_slotpos[2 * n + 1];
    const float w0 = ew[2 * n], w1 = ew[2 * n + 1];
    const uint4 a = *(const uint4*)&g_O[(size_t)p0 * HIDDEN + h8];
    const uint4 b = *(const uint4*)&g_O[(size_t)p1 * HIDDEN + h8];
    const uint32_t au[4] = {a.x, a.y, a.z, a.w};
    const uint32_t bu[4] = {b.x, b.y, b.z, b.w};
    float o[8];
#pragma unroll
    for (int j = 0; j < 4; j++) {
        float2 fa = __half22float2(*(const __half2*)&au[j]);
        float2 fb = __half22float2(*(const __half2*)&bu[j]);
        o[2 * j]     = w0 * fa.x + w1 * fb.x;
        o[2 * j + 1] = w0 * fa.y + w1 * fb.y;
    }
    float4* op = (float4*)(out + (size_t)n * HIDDEN + h8);
    op[0] = make_float4(o[0], o[1], o[2], o[3]);
    op[1] = make_float4(o[4], o[5], o[6], o[7]);
}

/* ------------------------------------------------------------------ */
/* launch: fork weight-convert branches onto side streams so they      */
/* overlap route/gather (branch A: Wg,Wu -> joins before gemm1) and    */
/* gemm1 itself (branch B: Wd -> joins before gemm2).                  */
/*                                                                     */
/* Streams/events are created EXACTLY ONCE, on the first call (the     */
/* correctness run, which precedes the harness's pre-capture memory    */
/* baseline). The capture call and every later call reuse the same     */
/* handles, so no allocation happens after the baseline and graph      */
/* teardown returns free memory to baseline (R10 failed because fresh  */
/* handles were created per call; the capture-call set stayed live     */
/* past graph destruction). The work submitted per call is identical   */
/* every call — this caches resources, it does not gate work.          */
/* ------------------------------------------------------------------ */
extern "C" void kernel_launch(void* const* d_in, const int* in_sizes, int n_in,
                              void* d_out, int out_size) {
    const float* tokens = (const float*)d_in[0];
    const int*   ei     = (const int*)d_in[1];
    const float* ew     = (const float*)d_in[2];
    const float* gw     = (const float*)d_in[3];
    const float* uw     = (const float*)d_in[4];
    const float* dw     = (const float*)d_in[5];
    float* out = (float*)d_out;
    (void)in_sizes; (void)n_in; (void)out_size;

    static bool s_init = false;
    static cudaStream_t sA, sB;
    static cudaEvent_t eR, eA, eB;
    static __half *wg, *wu, *wd;
    if (!s_init) {
        cudaGetSymbolAddress((void**)&wg, g_Wg);
        cudaGetSymbolAddress((void**)&wu, g_Wu);
        cudaGetSymbolAddress((void**)&wd, g_Wd);
        cudaFuncSetAttribute(k_gemm1, cudaFuncAttributeMaxDynamicSharedMemorySize, G1_SMEM);
        cudaFuncSetAttribute(k_gemm2, cudaFuncAttributeMaxDynamicSharedMemorySize, G2_SMEM);
        cudaStreamCreateWithFlags(&sA, cudaStreamNonBlocking);
        cudaStreamCreateWithFlags(&sB, cudaStreamNonBlocking);
        cudaEventCreateWithFlags(&eR, cudaEventDisableTiming);
        cudaEventCreateWithFlags(&eA, cudaEventDisableTiming);
        cudaEventCreateWithFlags(&eB, cudaEventDisableTiming);
        /* materialize stream pools & module state BEFORE the harness's
           pre-capture baseline: run one tiny launch on each side stream */
        k_cvt<<<1, 32, 0, sA>>>((const float4*)gw, (uint2*)wg, 0);
        k_cvt<<<1, 32, 0, sB>>>((const float4*)dw, (uint2*)wd, 0);
        cudaStreamSynchronize(sA);
        cudaStreamSynchronize(sB);
        s_init = true;
    }

    /* fork */
    cudaEventRecord(eR, 0);
    cudaStreamWaitEvent(sA, eR, 0);
    cudaStreamWaitEvent(sB, eR, 0);

    const int CVG = (W4 + 255) / 256;
    k_cvt<<<CVG, 256, 0, sA>>>((const float4*)gw, (uint2*)wg, W4);
    k_cvt<<<CVG, 256, 0, sA>>>((const float4*)uw, (uint2*)wu, W4);
    k_cvt<<<CVG, 256, 0, sB>>>((const float4*)dw, (uint2*)wd, W4);

    k_route<<<1, 1024>>>(ei);
    k_gather<<<(MAX_PAD * (HIDDEN / 4) + 255) / 256, 256>>>(tokens);

    /* join A (Wg,Wu) before gemm1 */
    cudaEventRecord(eA, sA);
    cudaStreamWaitEvent(0, eA, 0);
    k_gemm1<<<dim3(MTILES, INTER / 64), 256, G1_SMEM>>>();

    /* join B (Wd) before gemm2 — its convert overlapped gemm1 */
    cudaEventRecord(eB, sB);
    cudaStreamWaitEvent(0, eB, 0);
    k_gemm2<<<dim3(MTILES, HIDDEN / 128), 256, G2_SMEM>>>();

    k_combine<<<(N_TOKENS * HIDDEN / 8 + 255) / 256, 256>>>(ew, out);
}